// round 8
// baseline (speedup 1.0000x reference)
#include <cuda_runtime.h>
#include <cuda_bf16.h>
#include <stdint.h>
#include <math.h>

#define B_    4
#define N_    4096
#define K_    24
#define CIN_  64
#define COUT_ 128
#define BN_TOT (B_*N_)            // 16384
#define M_TOT  (BN_TOT*K_)        // 393216
#define EPS_  1e-5f

// ======================= scratch =======================
__device__ float g_xT[BN_TOT*CIN_];
__device__ int   g_idx[M_TOT];
__device__ float g_anchor[BN_TOT*COUT_];
__device__ float g_T[(size_t)M_TOT*COUT_];
__device__ float g_U[(size_t)M_TOT*COUT_];
__device__ float g_V[(size_t)M_TOT*COUT_];
__device__ float g_Z [BN_TOT*COUT_];
__device__ float g_Z1[BN_TOT*COUT_];
__device__ float g_Z2[BN_TOT*COUT_];
__device__ float g_const1[COUT_];
__device__ float g_ssum[5*128];
__device__ float g_ssq [5*128];
__device__ float g_coef[5*256];
__device__ float g_bsum[B_];
__device__ float g_bsq [B_];
__device__ float g_invstd[B_];
__device__ __nv_bfloat16 g_Wpk[6*2*128*128];   // 6 weights x (hi | lo), packed [o][k]

// ======================= asm helpers =======================
__device__ __forceinline__ uint32_t smem_u32(const void* p) {
    uint32_t a;
    asm("{ .reg .u64 t; cvta.to.shared.u64 t, %1; cvt.u32.u64 %0, t; }" : "=r"(a) : "l"(p));
    return a;
}
__device__ __forceinline__ void mma16816(float* c, const uint32_t* a, uint32_t b0, uint32_t b1) {
    asm volatile(
        "mma.sync.aligned.m16n8k16.row.col.f32.bf16.bf16.f32 "
        "{%0,%1,%2,%3}, {%4,%5,%6,%7}, {%8,%9}, {%0,%1,%2,%3};"
        : "+f"(c[0]), "+f"(c[1]), "+f"(c[2]), "+f"(c[3])
        : "r"(a[0]), "r"(a[1]), "r"(a[2]), "r"(a[3]), "r"(b0), "r"(b1));
}
__device__ __forceinline__ void ldsm4(uint32_t& r0, uint32_t& r1, uint32_t& r2, uint32_t& r3,
                                      uint32_t addr) {
    asm volatile("ldmatrix.sync.aligned.m8n8.x4.shared.b16 {%0,%1,%2,%3}, [%4];"
                 : "=r"(r0), "=r"(r1), "=r"(r2), "=r"(r3) : "r"(addr));
}

// ======================= utility kernels =======================
__global__ void zero_stats_kernel() {
    int i = threadIdx.x;              // 1024 threads
    if (i < 640) { g_ssum[i] = 0.f; g_ssq[i] = 0.f; }
    if (i < B_) { g_bsum[i] = 0.f; g_bsq[i] = 0.f; }
}

__global__ void transpose_x_kernel(const float* __restrict__ x) {
    __shared__ float tile[32][33];
    int b = blockIdx.z;
    int n0 = blockIdx.x * 32, c0 = blockIdx.y * 32;
    int tx = threadIdx.x, ty = threadIdx.y;
    #pragma unroll
    for (int rr = 0; rr < 4; ++rr) {
        int c = c0 + ty + rr*8;
        tile[ty + rr*8][tx] = x[((size_t)b*CIN_ + c)*N_ + n0 + tx];
    }
    __syncthreads();
    #pragma unroll
    for (int rr = 0; rr < 4; ++rr) {
        int n = n0 + ty + rr*8;
        g_xT[((size_t)b*N_ + n)*CIN_ + c0 + tx] = tile[tx][ty + rr*8];
    }
}

// split weight into bf16 hi/lo, packed [o][k]; hi tile then lo tile
__global__ void prep_w_kernel(const float* __restrict__ src,
                              const float* __restrict__ alpha,
                              int colOff, int srcStride, int KD,
                              __nv_bfloat16* __restrict__ dst) {
    int tot = 128 * KD;
    for (int i = blockIdx.x*blockDim.x + threadIdx.x; i < tot; i += gridDim.x*blockDim.x) {
        int o = i / KD, k = i - o*KD;
        float v = src[o*srcStride + colOff + k];
        if (alpha != nullptr) v *= alpha[k];
        __nv_bfloat16 hi = __float2bfloat16_rn(v);
        __nv_bfloat16 lo = __float2bfloat16_rn(v - __bfloat162float(hi));
        dst[i] = hi;
        dst[tot + i] = lo;
    }
}

__global__ void const1_kernel(const float* __restrict__ wt,
                              const float* __restrict__ beta,
                              const float* __restrict__ bt) {
    int o = threadIdx.x;
    float s = bt[o];
    #pragma unroll 8
    for (int c = 0; c < CIN_; ++c) s += wt[o*128 + c] * beta[c];
    g_const1[o] = s;
}

// ======================= kNN =======================
__global__ void knn_kernel(const float* __restrict__ xyz) {
    extern __shared__ float s[];
    float* sx = s;
    float* sy = s + N_;
    float* sz = s + 2*N_;
    float* sq = s + 3*N_;
    int b = blockIdx.y;
    const float* xb = xyz + (size_t)b*3*N_;
    for (int i = threadIdx.x; i < N_; i += blockDim.x) {
        float X = xb[i], Y = xb[N_ + i], Z = xb[2*N_ + i];
        sx[i] = X; sy[i] = Y; sz[i] = Z;
        sq[i] = X*X + Y*Y + Z*Z;
    }
    __syncthreads();
    int q = blockIdx.x * blockDim.x + threadIdx.x;
    float qx = sx[q], qy = sy[q], qz = sz[q], qs = sq[q];
    float kd[K_]; int ki[K_];
    #pragma unroll
    for (int t = 0; t < K_; ++t) { kd[t] = 3.4e38f; ki[t] = 0; }
    float worst = 3.4e38f;
    for (int j = 0; j < N_; ++j) {
        float d = qs + sq[j] - 2.f*(qx*sx[j] + qy*sy[j] + qz*sz[j]);
        if (d < worst) {
            int p = K_ - 1;
            while (p > 0 && kd[p-1] > d) { kd[p] = kd[p-1]; ki[p] = ki[p-1]; --p; }
            kd[p] = d; ki[p] = j;
            worst = kd[K_-1];
        }
    }
    int* o = g_idx + ((size_t)b*N_ + q)*K_;
    #pragma unroll
    for (int t = 0; t < K_; ++t) o[t] = ki[t];
}

// ======================= gather stats (per-batch std) — no D store ========
__global__ void gather_stat_kernel() {
    __shared__ float bs[8], bs2[8];
    int wid = threadIdx.x >> 5, lane = threadIdx.x & 31;
    int m = blockIdx.x * 8 + wid;
    int b = m / (N_*K_);
    int nk = m - b*(N_*K_);
    int n = nk / K_;
    int j = g_idx[m];
    const float2* src = reinterpret_cast<const float2*>(g_xT + ((size_t)b*N_ + j)*CIN_);
    const float2* anc = reinterpret_cast<const float2*>(g_xT + ((size_t)b*N_ + n)*CIN_);
    float2 gv = src[lane];
    float2 pv = anc[lane];
    float2 dv = make_float2(gv.x - pv.x, gv.y - pv.y);
    float s  = dv.x + dv.y;
    float s2 = dv.x*dv.x + dv.y*dv.y;
    #pragma unroll
    for (int off = 16; off; off >>= 1) {
        s  += __shfl_xor_sync(0xffffffffu, s,  off);
        s2 += __shfl_xor_sync(0xffffffffu, s2, off);
    }
    if (lane == 0) { bs[wid] = s; bs2[wid] = s2; }
    __syncthreads();
    if (threadIdx.x == 0) {
        float S = 0.f, S2 = 0.f;
        #pragma unroll
        for (int i = 0; i < 8; ++i) { S += bs[i]; S2 += bs2[i]; }
        atomicAdd(&g_bsum[b], S);
        atomicAdd(&g_bsq[b],  S2);
    }
}

__global__ void std_fin_kernel() {
    int b = threadIdx.x;
    if (b < B_) {
        const float cnt = (float)(N_*K_*CIN_);
        float mean = g_bsum[b] / cnt;
        float var  = (g_bsq[b] - cnt*mean*mean) / (cnt - 1.f);
        var = fmaxf(var, 0.f);
        g_invstd[b] = 1.f / (sqrtf(var) + EPS_);
    }
}

// ======================= mma.sync GEMM v2 =======================
// C[m, o] = src(A row m) @ W[o, :]^T  + epilogue.
// MODE: 0 = plain rows of A; 1 = affine+relu(A) with preA/preC; 2 = gather-diff
//       (A row m = g_xT[idx[m]] - g_xT[anchor(m)], KDIM=64 only).
// EPI:  0 = none, 1 = +bias, 2 = acc*invstd[b] + anchor + const1.
// ST:   fused per-channel sum/sumsq atomics.
// A staged per 64-col chunk (hi/lo bf16 split); B (hi/lo) staged fully.
// Fragments loaded via ldmatrix.x4 from padded smem (row stride 36/68 words).
template<int KDIM, int MODE, int EPI, bool ST>
__global__ __launch_bounds__(256, 2)
void mma_gemm(const float* __restrict__ A,
              const __nv_bfloat16* __restrict__ Wpk,
              float* __restrict__ C,
              const float* __restrict__ preA, const float* __restrict__ preC,
              const float* __restrict__ bias,
              const float* __restrict__ invstd,
              const float* __restrict__ anchor,
              const float* __restrict__ cnst,
              float* __restrict__ stat_sum,
              float* __restrict__ stat_sq) {
    constexpr int WA = 36;                 // words per A-chunk row (32 + 4 pad)
    constexpr int WB = KDIM/2 + 4;         // words per B row
    constexpr int NCHUNK = KDIM / 64;
    extern __shared__ uint32_t sm32[];
    __shared__ float s_stat[256];
    uint32_t* Ahi = sm32;
    uint32_t* Alo = sm32 + 128*WA;
    uint32_t* Bhi = sm32 + 2*128*WA;
    uint32_t* Blo = Bhi + 128*WB;
    const int tid = threadIdx.x;
    const int lane = tid & 31, wid = tid >> 5;
    const int wy = wid & 3, wx = wid >> 2;     // warp tile: rows wy*32, cols wx*64
    const int m0 = blockIdx.x * 128;

    if (ST && tid < 256) s_stat[tid] = 0.f;

    // ---- stage B (once) ----
    {
        constexpr int NB = 128 * KDIM / 8;     // uint4 per component tile
        const uint4* src = reinterpret_cast<const uint4*>(Wpk);
        #pragma unroll 2
        for (int i = tid; i < NB; i += 256) {
            int r = i / (KDIM/8), cb = i - r*(KDIM/8);
            *reinterpret_cast<uint4*>(Bhi + r*WB + cb*4) = src[i];
            *reinterpret_cast<uint4*>(Blo + r*WB + cb*4) = src[NB + i];
        }
    }

    // ---- fragment smem addresses (ldmatrix.x4 lane mapping) ----
    const uint32_t sbase = smem_u32(sm32);
    const int arow = wy*32 + ((lane>>3)&1)*8 + (lane&7);
    const uint32_t aAddr = sbase + (uint32_t)((arow*WA + (lane>>4)*4) * 4);
    const int brow = wx*64 + ((lane>>4)&1)*8 + (lane&7);
    const uint32_t bAddrH = sbase + (uint32_t)((2*128*WA + brow*WB + ((lane>>3)&1)*4) * 4);
    const uint32_t bAddrL = bAddrH + (uint32_t)(128*WB*4);

    float acc[2][8][4];
    #pragma unroll
    for (int mi = 0; mi < 2; ++mi)
        #pragma unroll
        for (int ni = 0; ni < 8; ++ni)
            #pragma unroll
            for (int j = 0; j < 4; ++j) acc[mi][ni][j] = 0.f;

    #pragma unroll
    for (int kc = 0; kc < NCHUNK; ++kc) {
        if (kc) __syncthreads();
        // ---- stage A chunk kc (128 rows x 64 cols), hi/lo split ----
        for (int id = tid; id < 1024; id += 256) {
            int r = id >> 3, cb = (id & 7) * 8;        // col within chunk
            float va[8];
            if (MODE == 2) {
                int m = m0 + r;
                int b = m / (N_*K_);
                int rem = m - b*(N_*K_);
                int n = rem / K_;
                int j = g_idx[m];
                const float4* gp = reinterpret_cast<const float4*>(g_xT + ((size_t)b*N_ + j)*CIN_ + cb);
                const float4* pp = reinterpret_cast<const float4*>(g_xT + ((size_t)b*N_ + n)*CIN_ + cb);
                float4 gv0 = gp[0], gv1 = gp[1], pv0 = pp[0], pv1 = pp[1];
                va[0]=gv0.x-pv0.x; va[1]=gv0.y-pv0.y; va[2]=gv0.z-pv0.z; va[3]=gv0.w-pv0.w;
                va[4]=gv1.x-pv1.x; va[5]=gv1.y-pv1.y; va[6]=gv1.z-pv1.z; va[7]=gv1.w-pv1.w;
            } else {
                int gcol = kc*64 + cb;
                const float4* ap = reinterpret_cast<const float4*>(A + (size_t)(m0 + r)*KDIM + gcol);
                float4 v0 = ap[0], v1 = ap[1];
                va[0]=v0.x; va[1]=v0.y; va[2]=v0.z; va[3]=v0.w;
                va[4]=v1.x; va[5]=v1.y; va[6]=v1.z; va[7]=v1.w;
                if (MODE == 1) {
                    const float4* pa = reinterpret_cast<const float4*>(preA + gcol);
                    const float4* pc = reinterpret_cast<const float4*>(preC + gcol);
                    float4 a0 = pa[0], a1 = pa[1], c0v = pc[0], c1v = pc[1];
                    float aa[8] = {a0.x,a0.y,a0.z,a0.w,a1.x,a1.y,a1.z,a1.w};
                    float cc[8] = {c0v.x,c0v.y,c0v.z,c0v.w,c1v.x,c1v.y,c1v.z,c1v.w};
                    #pragma unroll
                    for (int j = 0; j < 8; ++j) va[j] = fmaxf(fmaf(aa[j], va[j], cc[j]), 0.f);
                }
            }
            uint32_t h[4], l[4];
            #pragma unroll
            for (int j = 0; j < 4; ++j) {
                float a = va[2*j], b = va[2*j+1];
                __nv_bfloat16 ha = __float2bfloat16_rn(a);
                __nv_bfloat16 hb = __float2bfloat16_rn(b);
                __nv_bfloat16 la = __float2bfloat16_rn(a - __bfloat162float(ha));
                __nv_bfloat16 lb = __float2bfloat16_rn(b - __bfloat162float(hb));
                h[j] = (uint32_t)__bfloat16_as_ushort(ha) | ((uint32_t)__bfloat16_as_ushort(hb) << 16);
                l[j] = (uint32_t)__bfloat16_as_ushort(la) | ((uint32_t)__bfloat16_as_ushort(lb) << 16);
            }
            *reinterpret_cast<uint4*>(Ahi + r*WA + (cb >> 1)) = make_uint4(h[0], h[1], h[2], h[3]);
            *reinterpret_cast<uint4*>(Alo + r*WA + (cb >> 1)) = make_uint4(l[0], l[1], l[2], l[3]);
        }
        __syncthreads();

        // ---- mainloop: 4 k-steps over this chunk ----
        const uint32_t kcw = (uint32_t)(kc * 32 * 4);       // byte offset into B rows
        #pragma unroll
        for (int ks = 0; ks < 4; ++ks) {
            const uint32_t k0b = (uint32_t)(ks * 8 * 4);
            uint32_t afh[2][4], afl[2][4];
            ldsm4(afh[0][0], afh[0][1], afh[0][2], afh[0][3], aAddr + k0b);
            ldsm4(afh[1][0], afh[1][1], afh[1][2], afh[1][3], aAddr + (uint32_t)(16*WA*4) + k0b);
            ldsm4(afl[0][0], afl[0][1], afl[0][2], afl[0][3], aAddr + (uint32_t)(128*WA*4) + k0b);
            ldsm4(afl[1][0], afl[1][1], afl[1][2], afl[1][3], aAddr + (uint32_t)((128+16)*WA*4) + k0b);
            #pragma unroll
            for (int nb = 0; nb < 4; ++nb) {
                const uint32_t noff = (uint32_t)(nb*16*WB*4) + kcw + k0b;
                uint32_t h0, h1, h2, h3, l0, l1, l2, l3;
                ldsm4(h0, h1, h2, h3, bAddrH + noff);
                ldsm4(l0, l1, l2, l3, bAddrL + noff);
                #pragma unroll
                for (int mi = 0; mi < 2; ++mi) {
                    mma16816(acc[mi][2*nb],   afh[mi], h0, h1);
                    mma16816(acc[mi][2*nb+1], afh[mi], h2, h3);
                    mma16816(acc[mi][2*nb],   afh[mi], l0, l1);
                    mma16816(acc[mi][2*nb+1], afh[mi], l2, l3);
                    mma16816(acc[mi][2*nb],   afl[mi], h0, h1);
                    mma16816(acc[mi][2*nb+1], afl[mi], h2, h3);
                }
            }
        }
    }

    // ---- epilogue (+ fused per-channel stats) ----
    const int r = lane >> 2, q = lane & 3;
    float inv = 0.f;
    if (EPI == 2) inv = invstd[m0 / (N_*K_)];
    float cs[16], cq[16];
    if (ST) {
        #pragma unroll
        for (int j = 0; j < 16; ++j) { cs[j] = 0.f; cq[j] = 0.f; }
    }
    #pragma unroll
    for (int mi = 0; mi < 2; ++mi) {
        #pragma unroll
        for (int half = 0; half < 2; ++half) {
            const int row = m0 + wy*32 + mi*16 + r + half*8;
            float* crow = C + (size_t)row * COUT_;
            const float* arow = (EPI == 2) ? anchor + (size_t)(row / K_) * COUT_ : nullptr;
            #pragma unroll
            for (int ni = 0; ni < 8; ++ni) {
                const int col = wx*64 + ni*8 + q*2;
                float v0 = acc[mi][ni][half*2 + 0];
                float v1 = acc[mi][ni][half*2 + 1];
                if (EPI == 2) {
                    v0 = fmaf(v0, inv, arow[col]     + cnst[col]);
                    v1 = fmaf(v1, inv, arow[col + 1] + cnst[col + 1]);
                } else if (EPI == 1) {
                    v0 += bias[col];
                    v1 += bias[col + 1];
                }
                if (ST) {
                    cs[ni*2]     += v0;  cq[ni*2]     = fmaf(v0, v0, cq[ni*2]);
                    cs[ni*2 + 1] += v1;  cq[ni*2 + 1] = fmaf(v1, v1, cq[ni*2 + 1]);
                }
                *reinterpret_cast<float2*>(crow + col) = make_float2(v0, v1);
            }
        }
    }
    if (ST) {
        #pragma unroll
        for (int j = 0; j < 16; ++j) {
            #pragma unroll
            for (int off = 4; off < 32; off <<= 1) {
                cs[j] += __shfl_xor_sync(0xffffffffu, cs[j], off);
                cq[j] += __shfl_xor_sync(0xffffffffu, cq[j], off);
            }
        }
        if (r == 0) {
            #pragma unroll
            for (int j = 0; j < 16; ++j) {
                int col = wx*64 + (j >> 1)*8 + q*2 + (j & 1);
                atomicAdd(&s_stat[col], cs[j]);
                atomicAdd(&s_stat[128 + col], cq[j]);
            }
        }
        __syncthreads();
        if (tid < 128) {
            atomicAdd(&stat_sum[tid], s_stat[tid]);
            atomicAdd(&stat_sq[tid],  s_stat[128 + tid]);
        }
    }
}

// ======================= BN finalize =======================
__global__ void bn_fin_kernel(int stage, float inv_cnt,
                              const float* __restrict__ gamma,
                              const float* __restrict__ betab) {
    int o = threadIdx.x;
    float mean = g_ssum[stage*128 + o] * inv_cnt;
    float var  = g_ssq [stage*128 + o] * inv_cnt - mean*mean;
    var = fmaxf(var, 0.f);
    float a = gamma[o] / sqrtf(var + EPS_);
    g_coef[stage*256 + o]       = a;
    g_coef[stage*256 + 128 + o] = betab[o] - mean*a;
}

// ======================= residual + relu + maxpool over K =======================
__global__ void pool_kernel() {
    int bn = blockIdx.x;
    int o  = threadIdx.x;
    float A2 = g_coef[2*256 + o],       C2 = g_coef[2*256 + 128 + o];
    float A0 = g_coef[o],               C0 = g_coef[128 + o];
    const float* vp = g_V + (size_t)bn*K_*COUT_ + o;
    const float* tp = g_T + (size_t)bn*K_*COUT_ + o;
    float mx = -3.4e38f;
    #pragma unroll 8
    for (int k = 0; k < K_; ++k) {
        float v = fmaf(A2, vp[k*COUT_], C2) + fmaxf(fmaf(A0, tp[k*COUT_], C0), 0.f);
        mx = fmaxf(mx, fmaxf(v, 0.f));
    }
    g_Z[(size_t)bn*COUT_ + o] = mx;
}

// ======================= final BN + residual + relu + transpose =======================
__global__ void out_kernel(float* __restrict__ out) {
    __shared__ float tile[32][33];
    int b = blockIdx.z;
    int n0 = blockIdx.x * 32, o0 = blockIdx.y * 32;
    int tx = threadIdx.x, ty = threadIdx.y;
    float a5 = g_coef[4*256 + o0 + tx];
    float c5 = g_coef[4*256 + 128 + o0 + tx];
    #pragma unroll
    for (int rr = 0; rr < 4; ++rr) {
        int n  = n0 + ty + rr*8;
        size_t bn = (size_t)b*N_ + n;
        float v = fmaf(a5, g_Z2[bn*COUT_ + o0 + tx], c5) + g_Z[bn*COUT_ + o0 + tx];
        tile[ty + rr*8][tx] = fmaxf(v, 0.f);
    }
    __syncthreads();
    #pragma unroll
    for (int rr = 0; rr < 4; ++rr) {
        int o = o0 + ty + rr*8;
        out[((size_t)b*COUT_ + o)*N_ + n0 + tx] = tile[tx][ty + rr*8];
    }
}

// ======================= host =======================
extern "C" void kernel_launch(void* const* d_in, const int* in_sizes, int n_in,
                              void* d_out, int out_size) {
    const float* x    = (const float*)d_in[0];
    const float* xyz  = (const float*)d_in[1];
    const float* alpha= (const float*)d_in[2];
    const float* beta = (const float*)d_in[3];
    const float* wt   = (const float*)d_in[4];
    const float* bt   = (const float*)d_in[5];
    const float* gt   = (const float*)d_in[6];
    const float* btt  = (const float*)d_in[7];
    const float* w01  = (const float*)d_in[8];
    const float* b01  = (const float*)d_in[9];
    const float* g01  = (const float*)d_in[10];
    const float* bb01 = (const float*)d_in[11];
    const float* w02  = (const float*)d_in[12];
    const float* b02  = (const float*)d_in[13];
    const float* g02  = (const float*)d_in[14];
    const float* bb02 = (const float*)d_in[15];
    const float* w11  = (const float*)d_in[16];
    const float* b11  = (const float*)d_in[17];
    const float* g11  = (const float*)d_in[18];
    const float* bb11 = (const float*)d_in[19];
    const float* w12  = (const float*)d_in[20];
    const float* b12  = (const float*)d_in[21];
    const float* g12  = (const float*)d_in[22];
    const float* bb12 = (const float*)d_in[23];
    float* out = (float*)d_out;

    float *pXT, *pAnch, *pT, *pU, *pV, *pZ, *pZ1, *pZ2;
    float *pC1, *pSsum, *pSsq, *pCoef, *pInv;
    __nv_bfloat16* pWpk;
    cudaGetSymbolAddress((void**)&pXT,   g_xT);
    cudaGetSymbolAddress((void**)&pAnch, g_anchor);
    cudaGetSymbolAddress((void**)&pT,    g_T);
    cudaGetSymbolAddress((void**)&pU,    g_U);
    cudaGetSymbolAddress((void**)&pV,    g_V);
    cudaGetSymbolAddress((void**)&pZ,    g_Z);
    cudaGetSymbolAddress((void**)&pZ1,   g_Z1);
    cudaGetSymbolAddress((void**)&pZ2,   g_Z2);
    cudaGetSymbolAddress((void**)&pC1,   g_const1);
    cudaGetSymbolAddress((void**)&pSsum, g_ssum);
    cudaGetSymbolAddress((void**)&pSsq,  g_ssq);
    cudaGetSymbolAddress((void**)&pCoef, g_coef);
    cudaGetSymbolAddress((void**)&pInv,  g_invstd);
    cudaGetSymbolAddress((void**)&pWpk,  g_Wpk);

    const int WSLOT = 2*128*128;                         // bf16 elements per weight slot
    const int smem64  = (2*128*36 + 2*128*36) * 4;       // 73728
    const int smem128 = (2*128*36 + 2*128*68) * 4;       // 106496
    cudaFuncSetAttribute(knn_kernel, cudaFuncAttributeMaxDynamicSharedMemorySize, 65536);
    cudaFuncSetAttribute(mma_gemm<64,  0, 0, false>, cudaFuncAttributeMaxDynamicSharedMemorySize, smem64);
    cudaFuncSetAttribute(mma_gemm<64,  2, 2, true >, cudaFuncAttributeMaxDynamicSharedMemorySize, smem64);
    cudaFuncSetAttribute(mma_gemm<128, 1, 1, true >, cudaFuncAttributeMaxDynamicSharedMemorySize, smem128);
    cudaFuncSetAttribute(mma_gemm<128, 0, 1, true >, cudaFuncAttributeMaxDynamicSharedMemorySize, smem128);

    const float invM  = 1.f / (float)M_TOT;
    const float invBN = 1.f / (float)BN_TOT;

    // launches 1-5 (ncu -s 5 -c 1 captures launch 6 = knn_kernel)
    zero_stats_kernel<<<1, 1024>>>();
    prep_w_kernel<<<32, 256>>>(wt,  alpha,   0, 128,  64, pWpk + 0*WSLOT);
    prep_w_kernel<<<32, 256>>>(wt,  nullptr, 64, 128, 64, pWpk + 1*WSLOT);
    prep_w_kernel<<<64, 256>>>(w01, nullptr, 0, 128, 128, pWpk + 2*WSLOT);
    prep_w_kernel<<<64, 256>>>(w02, nullptr, 0, 128, 128, pWpk + 3*WSLOT);
    // launch 6: kNN (profiled this round)
    knn_kernel<<<dim3(N_/128, B_), 128, 65536>>>(xyz);
    prep_w_kernel<<<64, 256>>>(w11, nullptr, 0, 128, 128, pWpk + 4*WSLOT);
    prep_w_kernel<<<64, 256>>>(w12, nullptr, 0, 128, 128, pWpk + 5*WSLOT);
    transpose_x_kernel<<<dim3(N_/32, CIN_/32, B_), dim3(32, 8)>>>(x);
    const1_kernel<<<1, 128>>>(wt, beta, bt);

    gather_stat_kernel<<<M_TOT/8, 256>>>();
    std_fin_kernel<<<1, 32>>>();

    // anchor = pts @ Wp^T
    mma_gemm<64, 0, 0, false><<<BN_TOT/128, 256, smem64>>>(
        pXT, pWpk + 1*WSLOT, pAnch, nullptr, nullptr, nullptr,
        nullptr, nullptr, nullptr, nullptr, nullptr);

    // T = invstd_b * (gather-diff @ Wa^T) + anchor + const1   (stats 0 fused)
    mma_gemm<64, 2, 2, true><<<M_TOT/128, 256, smem64>>>(
        nullptr, pWpk + 0*WSLOT, pT, nullptr, nullptr, nullptr,
        pInv, pAnch, pC1, pSsum + 0, pSsq + 0);
    bn_fin_kernel<<<1, 128>>>(0, invM, gt, btt);

    // U = relu(bn0(T)) @ w01^T + b01   (stats 1 fused)
    mma_gemm<128, 1, 1, true><<<M_TOT/128, 256, smem128>>>(
        pT, pWpk + 2*WSLOT, pU, pCoef + 0, pCoef + 128, b01,
        nullptr, nullptr, nullptr, pSsum + 128, pSsq + 128);
    bn_fin_kernel<<<1, 128>>>(1, invM, g01, bb01);

    // V = relu(bn1(U)) @ w02^T + b02   (stats 2 fused)
    mma_gemm<128, 1, 1, true><<<M_TOT/128, 256, smem128>>>(
        pU, pWpk + 3*WSLOT, pV, pCoef + 256, pCoef + 384, b02,
        nullptr, nullptr, nullptr, pSsum + 256, pSsq + 256);
    bn_fin_kernel<<<1, 128>>>(2, invM, g02, bb02);

    pool_kernel<<<BN_TOT, 128>>>();

    // Z1 = Z @ w11^T + b11   (stats 3 fused)
    mma_gemm<128, 0, 1, true><<<BN_TOT/128, 256, smem128>>>(
        pZ, pWpk + 4*WSLOT, pZ1, nullptr, nullptr, b11,
        nullptr, nullptr, nullptr, pSsum + 384, pSsq + 384);
    bn_fin_kernel<<<1, 128>>>(3, invBN, g11, bb11);

    // Z2 = relu(bn3(Z1)) @ w12^T + b12   (stats 4 fused)
    mma_gemm<128, 1, 1, true><<<BN_TOT/128, 256, smem128>>>(
        pZ1, pWpk + 5*WSLOT, pZ2, pCoef + 3*256, pCoef + 3*256 + 128, b12,
        nullptr, nullptr, nullptr, pSsum + 512, pSsq + 512);
    bn_fin_kernel<<<1, 128>>>(4, invBN, g12, bb12);

    out_kernel<<<dim3(N_/32, COUT_/32, B_), dim3(32, 8)>>>(out);
}

// round 9
// speedup vs baseline: 1.2839x; 1.2839x over previous
#include <cuda_runtime.h>
#include <cuda_bf16.h>
#include <stdint.h>
#include <math.h>

#define B_    4
#define N_    4096
#define K_    24
#define CIN_  64
#define COUT_ 128
#define BN_TOT (B_*N_)            // 16384
#define M_TOT  (BN_TOT*K_)        // 393216
#define EPS_  1e-5f

// ======================= scratch =======================
__device__ float g_xT[BN_TOT*CIN_];
__device__ int   g_idx[M_TOT];
__device__ float g_D[(size_t)M_TOT*CIN_];
__device__ float g_anchor[BN_TOT*COUT_];
__device__ float g_T[(size_t)M_TOT*COUT_];
__device__ float g_U[(size_t)M_TOT*COUT_];
__device__ float g_V[(size_t)M_TOT*COUT_];
__device__ float g_Z [BN_TOT*COUT_];
__device__ float g_Z1[BN_TOT*COUT_];
__device__ float g_Z2[BN_TOT*COUT_];
__device__ float g_const1[COUT_];
__device__ float g_ssum[5*128];
__device__ float g_ssq [5*128];
__device__ float g_coef[5*256];
__device__ float g_bsum[B_];
__device__ float g_bsq [B_];
__device__ float g_invstd[B_];
__device__ float g_dummy[256];                 // shadow-GEMM stats sink
__device__ __nv_bfloat16 g_Wpk[6*2*128*128];   // 6 weights x (hi | lo), packed [o][k]

// ======================= asm helpers =======================
__device__ __forceinline__ uint32_t smem_u32(const void* p) {
    uint32_t a;
    asm("{ .reg .u64 t; cvta.to.shared.u64 t, %1; cvt.u32.u64 %0, t; }" : "=r"(a) : "l"(p));
    return a;
}
__device__ __forceinline__ void mma16816(float* c, const uint32_t* a, uint32_t b0, uint32_t b1) {
    asm volatile(
        "mma.sync.aligned.m16n8k16.row.col.f32.bf16.bf16.f32 "
        "{%0,%1,%2,%3}, {%4,%5,%6,%7}, {%8,%9}, {%0,%1,%2,%3};"
        : "+f"(c[0]), "+f"(c[1]), "+f"(c[2]), "+f"(c[3])
        : "r"(a[0]), "r"(a[1]), "r"(a[2]), "r"(a[3]), "r"(b0), "r"(b1));
}
__device__ __forceinline__ void ldsm4(uint32_t& r0, uint32_t& r1, uint32_t& r2, uint32_t& r3,
                                      uint32_t addr) {
    asm volatile("ldmatrix.sync.aligned.m8n8.x4.shared.b16 {%0,%1,%2,%3}, [%4];"
                 : "=r"(r0), "=r"(r1), "=r"(r2), "=r"(r3) : "r"(addr));
}

// ======================= utility kernels =======================
__global__ void zero_stats_kernel() {
    int i = threadIdx.x;              // 1024 threads
    if (i < 640) { g_ssum[i] = 0.f; g_ssq[i] = 0.f; }
    if (i < 256) g_dummy[i] = 0.f;
    if (i < B_) { g_bsum[i] = 0.f; g_bsq[i] = 0.f; }
}

__global__ void transpose_x_kernel(const float* __restrict__ x) {
    __shared__ float tile[32][33];
    int b = blockIdx.z;
    int n0 = blockIdx.x * 32, c0 = blockIdx.y * 32;
    int tx = threadIdx.x, ty = threadIdx.y;
    #pragma unroll
    for (int rr = 0; rr < 4; ++rr) {
        int c = c0 + ty + rr*8;
        tile[ty + rr*8][tx] = x[((size_t)b*CIN_ + c)*N_ + n0 + tx];
    }
    __syncthreads();
    #pragma unroll
    for (int rr = 0; rr < 4; ++rr) {
        int n = n0 + ty + rr*8;
        g_xT[((size_t)b*N_ + n)*CIN_ + c0 + tx] = tile[tx][ty + rr*8];
    }
}

// split weight into bf16 hi/lo, packed [o][k]; hi tile then lo tile
__global__ void prep_w_kernel(const float* __restrict__ src,
                              const float* __restrict__ alpha,
                              int colOff, int srcStride, int KD,
                              __nv_bfloat16* __restrict__ dst) {
    int tot = 128 * KD;
    for (int i = blockIdx.x*blockDim.x + threadIdx.x; i < tot; i += gridDim.x*blockDim.x) {
        int o = i / KD, k = i - o*KD;
        float v = src[o*srcStride + colOff + k];
        if (alpha != nullptr) v *= alpha[k];
        __nv_bfloat16 hi = __float2bfloat16_rn(v);
        __nv_bfloat16 lo = __float2bfloat16_rn(v - __bfloat162float(hi));
        dst[i] = hi;
        dst[tot + i] = lo;
    }
}

__global__ void const1_kernel(const float* __restrict__ wt,
                              const float* __restrict__ beta,
                              const float* __restrict__ bt) {
    int o = threadIdx.x;
    float s = bt[o];
    #pragma unroll 8
    for (int c = 0; c < CIN_; ++c) s += wt[o*128 + c] * beta[c];
    g_const1[o] = s;
}

// ======================= kNN =======================
__global__ void knn_kernel(const float* __restrict__ xyz) {
    extern __shared__ float s[];
    float* sx = s;
    float* sy = s + N_;
    float* sz = s + 2*N_;
    float* sq = s + 3*N_;
    int b = blockIdx.y;
    const float* xb = xyz + (size_t)b*3*N_;
    for (int i = threadIdx.x; i < N_; i += blockDim.x) {
        float X = xb[i], Y = xb[N_ + i], Z = xb[2*N_ + i];
        sx[i] = X; sy[i] = Y; sz[i] = Z;
        sq[i] = X*X + Y*Y + Z*Z;
    }
    __syncthreads();
    int q = blockIdx.x * blockDim.x + threadIdx.x;
    float qx = sx[q], qy = sy[q], qz = sz[q], qs = sq[q];
    float kd[K_]; int ki[K_];
    #pragma unroll
    for (int t = 0; t < K_; ++t) { kd[t] = 3.4e38f; ki[t] = 0; }
    float worst = 3.4e38f;
    for (int j = 0; j < N_; ++j) {
        float d = qs + sq[j] - 2.f*(qx*sx[j] + qy*sy[j] + qz*sz[j]);
        if (d < worst) {
            int p = K_ - 1;
            while (p > 0 && kd[p-1] > d) { kd[p] = kd[p-1]; ki[p] = ki[p-1]; --p; }
            kd[p] = d; ki[p] = j;
            worst = kd[K_-1];
        }
    }
    int* o = g_idx + ((size_t)b*N_ + q)*K_;
    #pragma unroll
    for (int t = 0; t < K_; ++t) o[t] = ki[t];
}

// ======================= gather + diff + batch std =======================
__global__ void gather_diff_kernel() {
    __shared__ float bs[8], bs2[8];
    int wid = threadIdx.x >> 5, lane = threadIdx.x & 31;
    int m = blockIdx.x * 8 + wid;
    int b = m / (N_*K_);
    int nk = m - b*(N_*K_);
    int n = nk / K_;
    int j = g_idx[m];
    const float2* src = reinterpret_cast<const float2*>(g_xT + ((size_t)b*N_ + j)*CIN_);
    const float2* anc = reinterpret_cast<const float2*>(g_xT + ((size_t)b*N_ + n)*CIN_);
    float2 gv = src[lane];
    float2 pv = anc[lane];
    float2 dv = make_float2(gv.x - pv.x, gv.y - pv.y);
    reinterpret_cast<float2*>(g_D + (size_t)m*CIN_)[lane] = dv;
    float s  = dv.x + dv.y;
    float s2 = dv.x*dv.x + dv.y*dv.y;
    #pragma unroll
    for (int off = 16; off; off >>= 1) {
        s  += __shfl_xor_sync(0xffffffffu, s,  off);
        s2 += __shfl_xor_sync(0xffffffffu, s2, off);
    }
    if (lane == 0) { bs[wid] = s; bs2[wid] = s2; }
    __syncthreads();
    if (threadIdx.x == 0) {
        float S = 0.f, S2 = 0.f;
        #pragma unroll
        for (int i = 0; i < 8; ++i) { S += bs[i]; S2 += bs2[i]; }
        atomicAdd(&g_bsum[b], S);
        atomicAdd(&g_bsq[b],  S2);
    }
}

__global__ void std_fin_kernel() {
    int b = threadIdx.x;
    if (b < B_) {
        const float cnt = (float)(N_*K_*CIN_);
        float mean = g_bsum[b] / cnt;
        float var  = (g_bsq[b] - cnt*mean*mean) / (cnt - 1.f);
        var = fmaxf(var, 0.f);
        g_invstd[b] = 1.f / (sqrtf(var) + EPS_);
    }
}

// ======================= mma.sync GEMM (ldmatrix fragments) ================
// C[m, o] = pre(A[m, :]) @ W[o, :]^T  + epilogue.
// EPI: 0 = none, 1 = +bias, 2 = acc*invstd[b] + anchor + const1
// ST:  fused per-channel sum/sumsq atomics.
// A/B staged monolithically in padded row-major bf16 smem, W words/row
// (W mod 32 == 4 -> ldmatrix row addresses land on distinct bank groups).
template<int KDIM, bool PRE, int EPI, bool ST>
__global__ __launch_bounds__(256, (KDIM == 64) ? 2 : 1)
void mma_gemm(const float* __restrict__ A,
              const __nv_bfloat16* __restrict__ Wpk,
              float* __restrict__ C,
              const float* __restrict__ preA, const float* __restrict__ preC,
              const float* __restrict__ bias,
              const float* __restrict__ invstd,
              const float* __restrict__ anchor,
              const float* __restrict__ cnst,
              float* __restrict__ stat_sum,
              float* __restrict__ stat_sq) {
    constexpr int W = KDIM/2 + 4;          // b32 words per row
    constexpr int TILEW = 128 * W;         // words per component tile
    extern __shared__ uint32_t sm32[];
    __shared__ float s_stat[256];
    uint32_t* Ahi = sm32;
    uint32_t* Alo = sm32 + TILEW;
    uint32_t* Bhi = sm32 + 2*TILEW;
    uint32_t* Blo = sm32 + 3*TILEW;
    const int tid = threadIdx.x;
    const int lane = tid & 31, wid = tid >> 5;
    const int wy = wid & 3, wx = wid >> 2;     // warp tile: rows wy*32, cols wx*64
    const int m0 = blockIdx.x * 128;

    if (ST && tid < 256) s_stat[tid] = 0.f;

    // ---- stage B (packed hi|lo -> padded) ----
    {
        constexpr int NB = 128 * KDIM / 8;     // uint4 per component tile
        const uint4* src = reinterpret_cast<const uint4*>(Wpk);
        #pragma unroll 2
        for (int i = tid; i < NB; i += 256) {
            int r = i / (KDIM/8), cb = i - r*(KDIM/8);
            *reinterpret_cast<uint4*>(Bhi + r*W + cb*4) = src[i];
            *reinterpret_cast<uint4*>(Blo + r*W + cb*4) = src[NB + i];
        }
    }
    // ---- stage A: fp32 load, optional affine+relu, bf16 hi/lo split ----
    {
        constexpr int NCH = KDIM / 8;
        for (int id = tid; id < 128*NCH; id += 256) {
            int r = id / NCH, cb = (id - r*NCH) * 8;
            const float4* ap = reinterpret_cast<const float4*>(A + (size_t)(m0 + r)*KDIM + cb);
            float4 v0 = ap[0], v1 = ap[1];
            float va[8] = {v0.x, v0.y, v0.z, v0.w, v1.x, v1.y, v1.z, v1.w};
            if (PRE) {
                const float4* pa = reinterpret_cast<const float4*>(preA + cb);
                const float4* pc = reinterpret_cast<const float4*>(preC + cb);
                float4 a0 = pa[0], a1 = pa[1], c0v = pc[0], c1v = pc[1];
                float aa[8] = {a0.x,a0.y,a0.z,a0.w,a1.x,a1.y,a1.z,a1.w};
                float cc[8] = {c0v.x,c0v.y,c0v.z,c0v.w,c1v.x,c1v.y,c1v.z,c1v.w};
                #pragma unroll
                for (int j = 0; j < 8; ++j) va[j] = fmaxf(fmaf(aa[j], va[j], cc[j]), 0.f);
            }
            uint32_t h[4], l[4];
            #pragma unroll
            for (int j = 0; j < 4; ++j) {
                float a = va[2*j], b = va[2*j+1];
                __nv_bfloat16 ha = __float2bfloat16_rn(a);
                __nv_bfloat16 hb = __float2bfloat16_rn(b);
                __nv_bfloat16 la = __float2bfloat16_rn(a - __bfloat162float(ha));
                __nv_bfloat16 lb = __float2bfloat16_rn(b - __bfloat162float(hb));
                h[j] = (uint32_t)__bfloat16_as_ushort(ha) | ((uint32_t)__bfloat16_as_ushort(hb) << 16);
                l[j] = (uint32_t)__bfloat16_as_ushort(la) | ((uint32_t)__bfloat16_as_ushort(lb) << 16);
            }
            *reinterpret_cast<uint4*>(Ahi + r*W + (cb >> 1)) = make_uint4(h[0], h[1], h[2], h[3]);
            *reinterpret_cast<uint4*>(Alo + r*W + (cb >> 1)) = make_uint4(l[0], l[1], l[2], l[3]);
        }
    }
    __syncthreads();

    // ---- fragment smem addresses (ldmatrix.x4 lane mapping) ----
    const uint32_t sbase = smem_u32(sm32);
    // A 16x16 tiles: lanes 0-15 -> rows 0-15 col 0; lanes 16-31 -> rows 0-15 col +16B
    const uint32_t aBase = sbase + (uint32_t)(((wy*32 + (lane & 15))*W + (lane >> 4)*4) * 4);
    // B 16x16 tiles: m0=n0-7/k0-7, m1=n0-7/k8-15, m2=n8-15/k0-7, m3=n8-15/k8-15
    const uint32_t bBase = sbase + (uint32_t)((2*TILEW +
                           (wx*64 + ((lane>>4)&1)*8 + (lane&7))*W + ((lane>>3)&1)*4) * 4);

    float acc[2][8][4];
    #pragma unroll
    for (int mi = 0; mi < 2; ++mi)
        #pragma unroll
        for (int ni = 0; ni < 8; ++ni)
            #pragma unroll
            for (int j = 0; j < 4; ++j) acc[mi][ni][j] = 0.f;

    #pragma unroll
    for (int ks = 0; ks < KDIM/16; ++ks) {
        const uint32_t koff = (uint32_t)(ks * 32);           // 8 words = 32B per kstep
        uint32_t afh[2][4], afl[2][4];
        ldsm4(afh[0][0], afh[0][1], afh[0][2], afh[0][3], aBase + koff);
        ldsm4(afh[1][0], afh[1][1], afh[1][2], afh[1][3], aBase + (uint32_t)(16*W*4) + koff);
        ldsm4(afl[0][0], afl[0][1], afl[0][2], afl[0][3], aBase + (uint32_t)(TILEW*4) + koff);
        ldsm4(afl[1][0], afl[1][1], afl[1][2], afl[1][3], aBase + (uint32_t)((TILEW + 16*W)*4) + koff);
        #pragma unroll
        for (int nb = 0; nb < 4; ++nb) {
            const uint32_t noff = (uint32_t)(nb*16*W*4) + koff;
            uint32_t h0, h1, h2, h3, l0, l1, l2, l3;
            ldsm4(h0, h1, h2, h3, bBase + noff);
            ldsm4(l0, l1, l2, l3, bBase + (uint32_t)(TILEW*4) + noff);
            #pragma unroll
            for (int mi = 0; mi < 2; ++mi) {
                mma16816(acc[mi][2*nb],   afh[mi], h0, h1);
                mma16816(acc[mi][2*nb+1], afh[mi], h2, h3);
                mma16816(acc[mi][2*nb],   afh[mi], l0, l1);
                mma16816(acc[mi][2*nb+1], afh[mi], l2, l3);
                mma16816(acc[mi][2*nb],   afl[mi], h0, h1);
                mma16816(acc[mi][2*nb+1], afl[mi], h2, h3);
            }
        }
    }

    // ---- epilogue (+ fused per-channel stats) ----
    const int r = lane >> 2, q = lane & 3;
    float inv = 0.f;
    if (EPI == 2) inv = invstd[m0 / (N_*K_)];
    float cs[16], cq[16];
    if (ST) {
        #pragma unroll
        for (int j = 0; j < 16; ++j) { cs[j] = 0.f; cq[j] = 0.f; }
    }
    #pragma unroll
    for (int mi = 0; mi < 2; ++mi) {
        #pragma unroll
        for (int half = 0; half < 2; ++half) {
            const int row = m0 + wy*32 + mi*16 + r + half*8;
            float* crow = C + (size_t)row * COUT_;
            const float* arow = (EPI == 2) ? anchor + (size_t)(row / K_) * COUT_ : nullptr;
            #pragma unroll
            for (int ni = 0; ni < 8; ++ni) {
                const int col = wx*64 + ni*8 + q*2;
                float v0 = acc[mi][ni][half*2 + 0];
                float v1 = acc[mi][ni][half*2 + 1];
                if (EPI == 2) {
                    v0 = fmaf(v0, inv, arow[col]     + cnst[col]);
                    v1 = fmaf(v1, inv, arow[col + 1] + cnst[col + 1]);
                } else if (EPI == 1) {
                    v0 += bias[col];
                    v1 += bias[col + 1];
                }
                if (ST) {
                    cs[ni*2]     += v0;  cq[ni*2]     = fmaf(v0, v0, cq[ni*2]);
                    cs[ni*2 + 1] += v1;  cq[ni*2 + 1] = fmaf(v1, v1, cq[ni*2 + 1]);
                }
                *reinterpret_cast<float2*>(crow + col) = make_float2(v0, v1);
            }
        }
    }
    if (ST) {
        #pragma unroll
        for (int j = 0; j < 16; ++j) {
            #pragma unroll
            for (int off = 4; off < 32; off <<= 1) {
                cs[j] += __shfl_xor_sync(0xffffffffu, cs[j], off);
                cq[j] += __shfl_xor_sync(0xffffffffu, cq[j], off);
            }
        }
        if (r == 0) {
            #pragma unroll
            for (int j = 0; j < 16; ++j) {
                int col = wx*64 + (j >> 1)*8 + q*2 + (j & 1);
                atomicAdd(&s_stat[col], cs[j]);
                atomicAdd(&s_stat[128 + col], cq[j]);
            }
        }
        __syncthreads();
        if (tid < 128) {
            atomicAdd(&stat_sum[tid], s_stat[tid]);
            atomicAdd(&stat_sq[tid],  s_stat[128 + tid]);
        }
    }
}

// ======================= BN finalize =======================
__global__ void bn_fin_kernel(int stage, float inv_cnt,
                              const float* __restrict__ gamma,
                              const float* __restrict__ betab) {
    int o = threadIdx.x;
    float mean = g_ssum[stage*128 + o] * inv_cnt;
    float var  = g_ssq [stage*128 + o] * inv_cnt - mean*mean;
    var = fmaxf(var, 0.f);
    float a = gamma[o] / sqrtf(var + EPS_);
    g_coef[stage*256 + o]       = a;
    g_coef[stage*256 + 128 + o] = betab[o] - mean*a;
}

// ======================= residual + relu + maxpool over K =======================
__global__ void pool_kernel() {
    int bn = blockIdx.x;
    int o  = threadIdx.x;
    float A2 = g_coef[2*256 + o],       C2 = g_coef[2*256 + 128 + o];
    float A0 = g_coef[o],               C0 = g_coef[128 + o];
    const float* vp = g_V + (size_t)bn*K_*COUT_ + o;
    const float* tp = g_T + (size_t)bn*K_*COUT_ + o;
    float mx = -3.4e38f;
    #pragma unroll 8
    for (int k = 0; k < K_; ++k) {
        float v = fmaf(A2, vp[k*COUT_], C2) + fmaxf(fmaf(A0, tp[k*COUT_], C0), 0.f);
        mx = fmaxf(mx, fmaxf(v, 0.f));
    }
    g_Z[(size_t)bn*COUT_ + o] = mx;
}

// ======================= final BN + residual + relu + transpose =======================
__global__ void out_kernel(float* __restrict__ out) {
    __shared__ float tile[32][33];
    int b = blockIdx.z;
    int n0 = blockIdx.x * 32, o0 = blockIdx.y * 32;
    int tx = threadIdx.x, ty = threadIdx.y;
    float a5 = g_coef[4*256 + o0 + tx];
    float c5 = g_coef[4*256 + 128 + o0 + tx];
    #pragma unroll
    for (int rr = 0; rr < 4; ++rr) {
        int n  = n0 + ty + rr*8;
        size_t bn = (size_t)b*N_ + n;
        float v = fmaf(a5, g_Z2[bn*COUT_ + o0 + tx], c5) + g_Z[bn*COUT_ + o0 + tx];
        tile[ty + rr*8][tx] = fmaxf(v, 0.f);
    }
    __syncthreads();
    #pragma unroll
    for (int rr = 0; rr < 4; ++rr) {
        int o = o0 + ty + rr*8;
        out[((size_t)b*COUT_ + o)*N_ + n0 + tx] = tile[tx][ty + rr*8];
    }
}

// ======================= host =======================
extern "C" void kernel_launch(void* const* d_in, const int* in_sizes, int n_in,
                              void* d_out, int out_size) {
    const float* x    = (const float*)d_in[0];
    const float* xyz  = (const float*)d_in[1];
    const float* alpha= (const float*)d_in[2];
    const float* beta = (const float*)d_in[3];
    const float* wt   = (const float*)d_in[4];
    const float* bt   = (const float*)d_in[5];
    const float* gt   = (const float*)d_in[6];
    const float* btt  = (const float*)d_in[7];
    const float* w01  = (const float*)d_in[8];
    const float* b01  = (const float*)d_in[9];
    const float* g01  = (const float*)d_in[10];
    const float* bb01 = (const float*)d_in[11];
    const float* w02  = (const float*)d_in[12];
    const float* b02  = (const float*)d_in[13];
    const float* g02  = (const float*)d_in[14];
    const float* bb02 = (const float*)d_in[15];
    const float* w11  = (const float*)d_in[16];
    const float* b11  = (const float*)d_in[17];
    const float* g11  = (const float*)d_in[18];
    const float* bb11 = (const float*)d_in[19];
    const float* w12  = (const float*)d_in[20];
    const float* b12  = (const float*)d_in[21];
    const float* g12  = (const float*)d_in[22];
    const float* bb12 = (const float*)d_in[23];
    float* out = (float*)d_out;

    float *pXT, *pD, *pAnch, *pT, *pU, *pV, *pZ, *pZ1, *pZ2;
    float *pC1, *pSsum, *pSsq, *pCoef, *pInv, *pDummy;
    __nv_bfloat16* pWpk;
    cudaGetSymbolAddress((void**)&pXT,   g_xT);
    cudaGetSymbolAddress((void**)&pD,    g_D);
    cudaGetSymbolAddress((void**)&pAnch, g_anchor);
    cudaGetSymbolAddress((void**)&pT,    g_T);
    cudaGetSymbolAddress((void**)&pU,    g_U);
    cudaGetSymbolAddress((void**)&pV,    g_V);
    cudaGetSymbolAddress((void**)&pZ,    g_Z);
    cudaGetSymbolAddress((void**)&pZ1,   g_Z1);
    cudaGetSymbolAddress((void**)&pZ2,   g_Z2);
    cudaGetSymbolAddress((void**)&pC1,   g_const1);
    cudaGetSymbolAddress((void**)&pSsum, g_ssum);
    cudaGetSymbolAddress((void**)&pSsq,  g_ssq);
    cudaGetSymbolAddress((void**)&pCoef, g_coef);
    cudaGetSymbolAddress((void**)&pInv,  g_invstd);
    cudaGetSymbolAddress((void**)&pDummy,g_dummy);
    cudaGetSymbolAddress((void**)&pWpk,  g_Wpk);

    const int WSLOT = 2*128*128;                 // bf16 elements per weight slot
    const int smem64  = 4 * 128 * 36 * 4;        // 73728
    const int smem128 = 4 * 128 * 68 * 4;        // 139264
    cudaFuncSetAttribute(knn_kernel, cudaFuncAttributeMaxDynamicSharedMemorySize, 65536);
    cudaFuncSetAttribute(mma_gemm<64,  false, 0, false>, cudaFuncAttributeMaxDynamicSharedMemorySize, smem64);
    cudaFuncSetAttribute(mma_gemm<64,  false, 2, true >, cudaFuncAttributeMaxDynamicSharedMemorySize, smem64);
    cudaFuncSetAttribute(mma_gemm<128, true,  1, true >, cudaFuncAttributeMaxDynamicSharedMemorySize, smem128);
    cudaFuncSetAttribute(mma_gemm<128, false, 1, true >, cudaFuncAttributeMaxDynamicSharedMemorySize, smem128);

    const float invM  = 1.f / (float)M_TOT;
    const float invBN = 1.f / (float)BN_TOT;

    // launches 1-3 (ncu captures the 4th launch = shadow GEMM)
    zero_stats_kernel<<<1, 1024>>>();
    prep_w_kernel<<<64, 256>>>(w01, nullptr, 0, 128, 128, pWpk + 2*WSLOT);
    prep_w_kernel<<<32, 256>>>(wt,  alpha,   0, 128,  64, pWpk + 0*WSLOT);

    // launch 4: SHADOW U-GEMM (profiling target; stale deterministic inputs,
    // writes g_U which the real U-GEMM later fully overwrites, stats -> dummy)
    mma_gemm<128, true, 1, true><<<1536, 256, smem128>>>(
        pT, pWpk + 2*WSLOT, pU, pCoef + 0, pCoef + 128, b01,
        nullptr, nullptr, nullptr, pDummy, pDummy + 128);

    prep_w_kernel<<<32, 256>>>(wt,  nullptr, 64, 128, 64, pWpk + 1*WSLOT);
    prep_w_kernel<<<64, 256>>>(w02, nullptr, 0, 128, 128, pWpk + 3*WSLOT);
    prep_w_kernel<<<64, 256>>>(w11, nullptr, 0, 128, 128, pWpk + 4*WSLOT);
    prep_w_kernel<<<64, 256>>>(w12, nullptr, 0, 128, 128, pWpk + 5*WSLOT);
    transpose_x_kernel<<<dim3(N_/32, CIN_/32, B_), dim3(32, 8)>>>(x);
    knn_kernel<<<dim3(N_/128, B_), 128, 65536>>>(xyz);
    const1_kernel<<<1, 128>>>(wt, beta, bt);

    gather_diff_kernel<<<M_TOT/8, 256>>>();
    std_fin_kernel<<<1, 32>>>();

    // anchor = pts @ Wp^T
    mma_gemm<64, false, 0, false><<<BN_TOT/128, 256, smem64>>>(
        pXT, pWpk + 1*WSLOT, pAnch, nullptr, nullptr, nullptr,
        nullptr, nullptr, nullptr, nullptr, nullptr);

    // T = invstd_b * (D @ Wa^T) + anchor + const1   (stats 0 fused)
    mma_gemm<64, false, 2, true><<<M_TOT/128, 256, smem64>>>(
        pD, pWpk + 0*WSLOT, pT, nullptr, nullptr, nullptr,
        pInv, pAnch, pC1, pSsum + 0, pSsq + 0);
    bn_fin_kernel<<<1, 128>>>(0, invM, gt, btt);

    // U = relu(bn0(T)) @ w01^T + b01   (stats 1 fused)
    mma_gemm<128, true, 1, true><<<M_TOT/128, 256, smem128>>>(
        pT, pWpk + 2*WSLOT, pU, pCoef + 0, pCoef + 128, b01,
        nullptr, nullptr, nullptr, pSsum + 128, pSsq + 128);
    bn_fin_kernel<<<1, 128>>>(1, invM, g01, bb01);

    // V = relu(bn1(U)) @ w02^T + b02   (stats 2 fused)
    mma_gemm<128, true, 1, true><<<M_TOT/128, 256, smem128>>>(
        pU, pWpk + 3*WSLOT, pV, pCoef + 256, pCoef + 384, b02,
        nullptr, nullptr, nullptr, pSsum + 256, pSsq + 256);
    bn_fin_kernel<<<1, 128>>>(2, invM, g02, bb02);

    pool_kernel<<<BN_TOT, 128>>>();

    // Z1 = Z @ w11^T + b11   (stats 3 fused)
    mma_gemm<128, false, 1, true><<<BN_TOT/128, 256, smem128>>>(
        pZ, pWpk + 4*WSLOT, pZ1, nullptr, nullptr, b11,
        nullptr, nullptr, nullptr, pSsum + 384, pSsq + 384);
    bn_fin_kernel<<<1, 128>>>(3, invBN, g11, bb11);

    // Z2 = relu(bn3(Z1)) @ w12^T + b12   (stats 4 fused)
    mma_gemm<128, true, 1, true><<<M_TOT ? BN_TOT/128 : 0, 256, smem128>>>(
        pZ1, pWpk + 5*WSLOT, pZ2, pCoef + 3*256, pCoef + 3*256 + 128, b12,
        nullptr, nullptr, nullptr, pSsum + 512, pSsq + 512);
    bn_fin_kernel<<<1, 128>>>(4, invBN, g12, bb12);

    out_kernel<<<dim3(N_/32, COUT_/32, B_), dim3(32, 8)>>>(out);
}

// round 10
// speedup vs baseline: 1.3957x; 1.0870x over previous
#include <cuda_runtime.h>
#include <cuda_bf16.h>
#include <stdint.h>
#include <math.h>

#define B_    4
#define N_    4096
#define K_    24
#define CIN_  64
#define COUT_ 128
#define BN_TOT (B_*N_)            // 16384
#define M_TOT  (BN_TOT*K_)        // 393216
#define EPS_  1e-5f

// ======================= scratch =======================
__device__ float g_xT[BN_TOT*CIN_];
__device__ int   g_idx[M_TOT];
__device__ float g_D[(size_t)M_TOT*CIN_];
__device__ float g_anchor[BN_TOT*COUT_];
__device__ float g_T[(size_t)M_TOT*COUT_];
__device__ float g_U[(size_t)M_TOT*COUT_];
__device__ float g_V[(size_t)M_TOT*COUT_];
__device__ float g_Z [BN_TOT*COUT_];
__device__ float g_Z1[BN_TOT*COUT_];
__device__ float g_Z2[BN_TOT*COUT_];
__device__ float g_const1[COUT_];
__device__ float g_ssum[5*128];
__device__ float g_ssq [5*128];
__device__ float g_coef[5*256];
__device__ float g_bsum[B_];
__device__ float g_bsq [B_];
__device__ float g_invstd[B_];
__device__ float g_dummy[256];                 // shadow-GEMM stats sink
__device__ __nv_bfloat16 g_Wpk[6*2*128*128];   // 6 weights x (hi | lo), packed [o][k]

// ======================= asm helpers =======================
__device__ __forceinline__ uint32_t smem_u32(const void* p) {
    uint32_t a;
    asm("{ .reg .u64 t; cvta.to.shared.u64 t, %1; cvt.u32.u64 %0, t; }" : "=r"(a) : "l"(p));
    return a;
}
__device__ __forceinline__ void mma16816(float* c, const uint32_t* a, uint32_t b0, uint32_t b1) {
    asm volatile(
        "mma.sync.aligned.m16n8k16.row.col.f32.bf16.bf16.f32 "
        "{%0,%1,%2,%3}, {%4,%5,%6,%7}, {%8,%9}, {%0,%1,%2,%3};"
        : "+f"(c[0]), "+f"(c[1]), "+f"(c[2]), "+f"(c[3])
        : "r"(a[0]), "r"(a[1]), "r"(a[2]), "r"(a[3]), "r"(b0), "r"(b1));
}
__device__ __forceinline__ void ldsm4(uint32_t& r0, uint32_t& r1, uint32_t& r2, uint32_t& r3,
                                      uint32_t addr) {
    asm volatile("ldmatrix.sync.aligned.m8n8.x4.shared.b16 {%0,%1,%2,%3}, [%4];"
                 : "=r"(r0), "=r"(r1), "=r"(r2), "=r"(r3) : "r"(addr));
}

// ======================= utility kernels =======================
__global__ void zero_stats_kernel() {
    int i = threadIdx.x;              // 1024 threads
    if (i < 640) { g_ssum[i] = 0.f; g_ssq[i] = 0.f; }
    if (i < 256) g_dummy[i] = 0.f;
    if (i < B_) { g_bsum[i] = 0.f; g_bsq[i] = 0.f; }
}

__global__ void transpose_x_kernel(const float* __restrict__ x) {
    __shared__ float tile[32][33];
    int b = blockIdx.z;
    int n0 = blockIdx.x * 32, c0 = blockIdx.y * 32;
    int tx = threadIdx.x, ty = threadIdx.y;
    #pragma unroll
    for (int rr = 0; rr < 4; ++rr) {
        int c = c0 + ty + rr*8;
        tile[ty + rr*8][tx] = x[((size_t)b*CIN_ + c)*N_ + n0 + tx];
    }
    __syncthreads();
    #pragma unroll
    for (int rr = 0; rr < 4; ++rr) {
        int n = n0 + ty + rr*8;
        g_xT[((size_t)b*N_ + n)*CIN_ + c0 + tx] = tile[tx][ty + rr*8];
    }
}

// split weight into bf16 hi/lo, packed [o][k]; hi tile then lo tile
__global__ void prep_w_kernel(const float* __restrict__ src,
                              const float* __restrict__ alpha,
                              int colOff, int srcStride, int KD,
                              __nv_bfloat16* __restrict__ dst) {
    int tot = 128 * KD;
    for (int i = blockIdx.x*blockDim.x + threadIdx.x; i < tot; i += gridDim.x*blockDim.x) {
        int o = i / KD, k = i - o*KD;
        float v = src[o*srcStride + colOff + k];
        if (alpha != nullptr) v *= alpha[k];
        __nv_bfloat16 hi = __float2bfloat16_rn(v);
        __nv_bfloat16 lo = __float2bfloat16_rn(v - __bfloat162float(hi));
        dst[i] = hi;
        dst[tot + i] = lo;
    }
}

__global__ void const1_kernel(const float* __restrict__ wt,
                              const float* __restrict__ beta,
                              const float* __restrict__ bt) {
    int o = threadIdx.x;
    float s = bt[o];
    #pragma unroll 8
    for (int c = 0; c < CIN_; ++c) s += wt[o*128 + c] * beta[c];
    g_const1[o] = s;
}

// ======================= kNN =======================
__global__ void knn_kernel(const float* __restrict__ xyz) {
    extern __shared__ float s[];
    float* sx = s;
    float* sy = s + N_;
    float* sz = s + 2*N_;
    float* sq = s + 3*N_;
    int b = blockIdx.y;
    const float* xb = xyz + (size_t)b*3*N_;
    for (int i = threadIdx.x; i < N_; i += blockDim.x) {
        float X = xb[i], Y = xb[N_ + i], Z = xb[2*N_ + i];
        sx[i] = X; sy[i] = Y; sz[i] = Z;
        sq[i] = X*X + Y*Y + Z*Z;
    }
    __syncthreads();
    int q = blockIdx.x * blockDim.x + threadIdx.x;
    float qx = sx[q], qy = sy[q], qz = sz[q], qs = sq[q];
    float kd[K_]; int ki[K_];
    #pragma unroll
    for (int t = 0; t < K_; ++t) { kd[t] = 3.4e38f; ki[t] = 0; }
    float worst = 3.4e38f;
    for (int j = 0; j < N_; ++j) {
        float d = qs + sq[j] - 2.f*(qx*sx[j] + qy*sy[j] + qz*sz[j]);
        if (d < worst) {
            int p = K_ - 1;
            while (p > 0 && kd[p-1] > d) { kd[p] = kd[p-1]; ki[p] = ki[p-1]; --p; }
            kd[p] = d; ki[p] = j;
            worst = kd[K_-1];
        }
    }
    int* o = g_idx + ((size_t)b*N_ + q)*K_;
    #pragma unroll
    for (int t = 0; t < K_; ++t) o[t] = ki[t];
}

// ======================= gather + diff + batch std =======================
__global__ void gather_diff_kernel() {
    __shared__ float bs[8], bs2[8];
    int wid = threadIdx.x >> 5, lane = threadIdx.x & 31;
    int m = blockIdx.x * 8 + wid;
    int b = m / (N_*K_);
    int nk = m - b*(N_*K_);
    int n = nk / K_;
    int j = g_idx[m];
    const float2* src = reinterpret_cast<const float2*>(g_xT + ((size_t)b*N_ + j)*CIN_);
    const float2* anc = reinterpret_cast<const float2*>(g_xT + ((size_t)b*N_ + n)*CIN_);
    float2 gv = src[lane];
    float2 pv = anc[lane];
    float2 dv = make_float2(gv.x - pv.x, gv.y - pv.y);
    reinterpret_cast<float2*>(g_D + (size_t)m*CIN_)[lane] = dv;
    float s  = dv.x + dv.y;
    float s2 = dv.x*dv.x + dv.y*dv.y;
    #pragma unroll
    for (int off = 16; off; off >>= 1) {
        s  += __shfl_xor_sync(0xffffffffu, s,  off);
        s2 += __shfl_xor_sync(0xffffffffu, s2, off);
    }
    if (lane == 0) { bs[wid] = s; bs2[wid] = s2; }
    __syncthreads();
    if (threadIdx.x == 0) {
        float S = 0.f, S2 = 0.f;
        #pragma unroll
        for (int i = 0; i < 8; ++i) { S += bs[i]; S2 += bs2[i]; }
        atomicAdd(&g_bsum[b], S);
        atomicAdd(&g_bsq[b],  S2);
    }
}

__global__ void std_fin_kernel() {
    int b = threadIdx.x;
    if (b < B_) {
        const float cnt = (float)(N_*K_*CIN_);
        float mean = g_bsum[b] / cnt;
        float var  = (g_bsq[b] - cnt*mean*mean) / (cnt - 1.f);
        var = fmaxf(var, 0.f);
        g_invstd[b] = 1.f / (sqrtf(var) + EPS_);
    }
}

// ======================= mma.sync GEMM (M-tile 64, 2 CTAs/SM) ==============
// C[m, o] = pre(A[m, :]) @ W[o, :]^T  + epilogue.   CTA tile: 64 x 128.
// Warp tile: 32 x 32 (wy = wid&1 row group, wx = wid>>1 col group).
// EPI: 0 = none, 1 = +bias, 2 = acc*invstd[b] + anchor + const1
// ST:  fused per-channel sum/sumsq atomics.
template<int KDIM, bool PRE, int EPI, bool ST>
__global__ __launch_bounds__(256, 2)
void mma_gemm(const float* __restrict__ A,
              const __nv_bfloat16* __restrict__ Wpk,
              float* __restrict__ C,
              const float* __restrict__ preA, const float* __restrict__ preC,
              const float* __restrict__ bias,
              const float* __restrict__ invstd,
              const float* __restrict__ anchor,
              const float* __restrict__ cnst,
              float* __restrict__ stat_sum,
              float* __restrict__ stat_sq) {
    constexpr int W = KDIM/2 + 4;          // b32 words per row
    constexpr int TILEA = 64 * W;          // words per A component tile
    constexpr int TILEB = 128 * W;         // words per B component tile
    extern __shared__ uint32_t sm32[];
    __shared__ float s_stat[256];
    uint32_t* Ahi = sm32;
    uint32_t* Alo = sm32 + TILEA;
    uint32_t* Bhi = sm32 + 2*TILEA;
    uint32_t* Blo = Bhi + TILEB;
    const int tid = threadIdx.x;
    const int lane = tid & 31, wid = tid >> 5;
    const int wy = wid & 1, wx = wid >> 1;     // warp tile: rows wy*32, cols wx*32
    const int m0 = blockIdx.x * 64;

    if (ST && tid < 256) s_stat[tid] = 0.f;

    // ---- stage B (packed hi|lo -> padded) ----
    {
        constexpr int NB = 128 * KDIM / 8;     // uint4 per component tile
        const uint4* src = reinterpret_cast<const uint4*>(Wpk);
        #pragma unroll 2
        for (int i = tid; i < NB; i += 256) {
            int r = i / (KDIM/8), cb = i - r*(KDIM/8);
            *reinterpret_cast<uint4*>(Bhi + r*W + cb*4) = src[i];
            *reinterpret_cast<uint4*>(Blo + r*W + cb*4) = src[NB + i];
        }
    }
    // ---- stage A: fp32 load, optional affine+relu, bf16 hi/lo split ----
    {
        constexpr int NCH = KDIM / 8;
        for (int id = tid; id < 64*NCH; id += 256) {
            int r = id / NCH, cb = (id - r*NCH) * 8;
            const float4* ap = reinterpret_cast<const float4*>(A + (size_t)(m0 + r)*KDIM + cb);
            float4 v0 = ap[0], v1 = ap[1];
            float va[8] = {v0.x, v0.y, v0.z, v0.w, v1.x, v1.y, v1.z, v1.w};
            if (PRE) {
                const float4* pa = reinterpret_cast<const float4*>(preA + cb);
                const float4* pc = reinterpret_cast<const float4*>(preC + cb);
                float4 a0 = pa[0], a1 = pa[1], c0v = pc[0], c1v = pc[1];
                float aa[8] = {a0.x,a0.y,a0.z,a0.w,a1.x,a1.y,a1.z,a1.w};
                float cc[8] = {c0v.x,c0v.y,c0v.z,c0v.w,c1v.x,c1v.y,c1v.z,c1v.w};
                #pragma unroll
                for (int j = 0; j < 8; ++j) va[j] = fmaxf(fmaf(aa[j], va[j], cc[j]), 0.f);
            }
            uint32_t h[4], l[4];
            #pragma unroll
            for (int j = 0; j < 4; ++j) {
                float a = va[2*j], b = va[2*j+1];
                __nv_bfloat16 ha = __float2bfloat16_rn(a);
                __nv_bfloat16 hb = __float2bfloat16_rn(b);
                __nv_bfloat16 la = __float2bfloat16_rn(a - __bfloat162float(ha));
                __nv_bfloat16 lb = __float2bfloat16_rn(b - __bfloat162float(hb));
                h[j] = (uint32_t)__bfloat16_as_ushort(ha) | ((uint32_t)__bfloat16_as_ushort(hb) << 16);
                l[j] = (uint32_t)__bfloat16_as_ushort(la) | ((uint32_t)__bfloat16_as_ushort(lb) << 16);
            }
            *reinterpret_cast<uint4*>(Ahi + r*W + (cb >> 1)) = make_uint4(h[0], h[1], h[2], h[3]);
            *reinterpret_cast<uint4*>(Alo + r*W + (cb >> 1)) = make_uint4(l[0], l[1], l[2], l[3]);
        }
    }
    __syncthreads();

    // ---- fragment smem addresses (ldmatrix.x4 lane mapping) ----
    const uint32_t sbase = smem_u32(sm32);
    const uint32_t aBase = sbase + (uint32_t)(((wy*32 + (lane & 15))*W + (lane >> 4)*4) * 4);
    const uint32_t bBase = sbase + (uint32_t)((2*TILEA +
                           (wx*32 + ((lane>>4)&1)*8 + (lane&7))*W + ((lane>>3)&1)*4) * 4);

    float acc[2][4][4];
    #pragma unroll
    for (int mi = 0; mi < 2; ++mi)
        #pragma unroll
        for (int ni = 0; ni < 4; ++ni)
            #pragma unroll
            for (int j = 0; j < 4; ++j) acc[mi][ni][j] = 0.f;

    #pragma unroll
    for (int ks = 0; ks < KDIM/16; ++ks) {
        const uint32_t koff = (uint32_t)(ks * 32);           // 8 words = 32B per kstep
        uint32_t afh[2][4], afl[2][4];
        ldsm4(afh[0][0], afh[0][1], afh[0][2], afh[0][3], aBase + koff);
        ldsm4(afh[1][0], afh[1][1], afh[1][2], afh[1][3], aBase + (uint32_t)(16*W*4) + koff);
        ldsm4(afl[0][0], afl[0][1], afl[0][2], afl[0][3], aBase + (uint32_t)(TILEA*4) + koff);
        ldsm4(afl[1][0], afl[1][1], afl[1][2], afl[1][3], aBase + (uint32_t)((TILEA + 16*W)*4) + koff);
        #pragma unroll
        for (int nb = 0; nb < 2; ++nb) {
            const uint32_t noff = (uint32_t)(nb*16*W*4) + koff;
            uint32_t h0, h1, h2, h3, l0, l1, l2, l3;
            ldsm4(h0, h1, h2, h3, bBase + noff);
            ldsm4(l0, l1, l2, l3, bBase + (uint32_t)(TILEB*4) + noff);
            #pragma unroll
            for (int mi = 0; mi < 2; ++mi) {
                mma16816(acc[mi][2*nb],   afh[mi], h0, h1);
                mma16816(acc[mi][2*nb+1], afh[mi], h2, h3);
                mma16816(acc[mi][2*nb],   afh[mi], l0, l1);
                mma16816(acc[mi][2*nb+1], afh[mi], l2, l3);
                mma16816(acc[mi][2*nb],   afl[mi], h0, h1);
                mma16816(acc[mi][2*nb+1], afl[mi], h2, h3);
            }
        }
    }

    // ---- epilogue (+ fused per-channel stats) ----
    const int r = lane >> 2, q = lane & 3;
    float inv = 0.f;
    if (EPI == 2) inv = invstd[m0 / (N_*K_)];
    float cs[8], cq[8];
    if (ST) {
        #pragma unroll
        for (int j = 0; j < 8; ++j) { cs[j] = 0.f; cq[j] = 0.f; }
    }
    #pragma unroll
    for (int mi = 0; mi < 2; ++mi) {
        #pragma unroll
        for (int half = 0; half < 2; ++half) {
            const int row = m0 + wy*32 + mi*16 + r + half*8;
            float* crow = C + (size_t)row * COUT_;
            const float* arow = (EPI == 2) ? anchor + (size_t)(row / K_) * COUT_ : nullptr;
            #pragma unroll
            for (int ni = 0; ni < 4; ++ni) {
                const int col = wx*32 + ni*8 + q*2;
                float v0 = acc[mi][ni][half*2 + 0];
                float v1 = acc[mi][ni][half*2 + 1];
                if (EPI == 2) {
                    v0 = fmaf(v0, inv, arow[col]     + cnst[col]);
                    v1 = fmaf(v1, inv, arow[col + 1] + cnst[col + 1]);
                } else if (EPI == 1) {
                    v0 += bias[col];
                    v1 += bias[col + 1];
                }
                if (ST) {
                    cs[ni*2]     += v0;  cq[ni*2]     = fmaf(v0, v0, cq[ni*2]);
                    cs[ni*2 + 1] += v1;  cq[ni*2 + 1] = fmaf(v1, v1, cq[ni*2 + 1]);
                }
                *reinterpret_cast<float2*>(crow + col) = make_float2(v0, v1);
            }
        }
    }
    if (ST) {
        #pragma unroll
        for (int j = 0; j < 8; ++j) {
            #pragma unroll
            for (int off = 4; off < 32; off <<= 1) {
                cs[j] += __shfl_xor_sync(0xffffffffu, cs[j], off);
                cq[j] += __shfl_xor_sync(0xffffffffu, cq[j], off);
            }
        }
        if (r == 0) {
            #pragma unroll
            for (int j = 0; j < 8; ++j) {
                int col = wx*32 + (j >> 1)*8 + q*2 + (j & 1);
                atomicAdd(&s_stat[col], cs[j]);
                atomicAdd(&s_stat[128 + col], cq[j]);
            }
        }
        __syncthreads();
        if (tid < 128) {
            atomicAdd(&stat_sum[tid], s_stat[tid]);
            atomicAdd(&stat_sq[tid],  s_stat[128 + tid]);
        }
    }
}

// ======================= BN finalize =======================
__global__ void bn_fin_kernel(int stage, float inv_cnt,
                              const float* __restrict__ gamma,
                              const float* __restrict__ betab) {
    int o = threadIdx.x;
    float mean = g_ssum[stage*128 + o] * inv_cnt;
    float var  = g_ssq [stage*128 + o] * inv_cnt - mean*mean;
    var = fmaxf(var, 0.f);
    float a = gamma[o] / sqrtf(var + EPS_);
    g_coef[stage*256 + o]       = a;
    g_coef[stage*256 + 128 + o] = betab[o] - mean*a;
}

// ======================= residual + relu + maxpool over K =======================
__global__ void pool_kernel() {
    int bn = blockIdx.x;
    int o  = threadIdx.x;
    float A2 = g_coef[2*256 + o],       C2 = g_coef[2*256 + 128 + o];
    float A0 = g_coef[o],               C0 = g_coef[128 + o];
    const float* vp = g_V + (size_t)bn*K_*COUT_ + o;
    const float* tp = g_T + (size_t)bn*K_*COUT_ + o;
    float mx = -3.4e38f;
    #pragma unroll 8
    for (int k = 0; k < K_; ++k) {
        float v = fmaf(A2, vp[k*COUT_], C2) + fmaxf(fmaf(A0, tp[k*COUT_], C0), 0.f);
        mx = fmaxf(mx, fmaxf(v, 0.f));
    }
    g_Z[(size_t)bn*COUT_ + o] = mx;
}

// ======================= final BN + residual + relu + transpose =======================
__global__ void out_kernel(float* __restrict__ out) {
    __shared__ float tile[32][33];
    int b = blockIdx.z;
    int n0 = blockIdx.x * 32, o0 = blockIdx.y * 32;
    int tx = threadIdx.x, ty = threadIdx.y;
    float a5 = g_coef[4*256 + o0 + tx];
    float c5 = g_coef[4*256 + 128 + o0 + tx];
    #pragma unroll
    for (int rr = 0; rr < 4; ++rr) {
        int n  = n0 + ty + rr*8;
        size_t bn = (size_t)b*N_ + n;
        float v = fmaf(a5, g_Z2[bn*COUT_ + o0 + tx], c5) + g_Z[bn*COUT_ + o0 + tx];
        tile[ty + rr*8][tx] = fmaxf(v, 0.f);
    }
    __syncthreads();
    #pragma unroll
    for (int rr = 0; rr < 4; ++rr) {
        int o = o0 + ty + rr*8;
        out[((size_t)b*COUT_ + o)*N_ + n0 + tx] = tile[tx][ty + rr*8];
    }
}

// ======================= host =======================
extern "C" void kernel_launch(void* const* d_in, const int* in_sizes, int n_in,
                              void* d_out, int out_size) {
    const float* x    = (const float*)d_in[0];
    const float* xyz  = (const float*)d_in[1];
    const float* alpha= (const float*)d_in[2];
    const float* beta = (const float*)d_in[3];
    const float* wt   = (const float*)d_in[4];
    const float* bt   = (const float*)d_in[5];
    const float* gt   = (const float*)d_in[6];
    const float* btt  = (const float*)d_in[7];
    const float* w01  = (const float*)d_in[8];
    const float* b01  = (const float*)d_in[9];
    const float* g01  = (const float*)d_in[10];
    const float* bb01 = (const float*)d_in[11];
    const float* w02  = (const float*)d_in[12];
    const float* b02  = (const float*)d_in[13];
    const float* g02  = (const float*)d_in[14];
    const float* bb02 = (const float*)d_in[15];
    const float* w11  = (const float*)d_in[16];
    const float* b11  = (const float*)d_in[17];
    const float* g11  = (const float*)d_in[18];
    const float* bb11 = (const float*)d_in[19];
    const float* w12  = (const float*)d_in[20];
    const float* b12  = (const float*)d_in[21];
    const float* g12  = (const float*)d_in[22];
    const float* bb12 = (const float*)d_in[23];
    float* out = (float*)d_out;

    float *pXT, *pD, *pAnch, *pT, *pU, *pV, *pZ, *pZ1, *pZ2;
    float *pC1, *pSsum, *pSsq, *pCoef, *pInv, *pDummy;
    __nv_bfloat16* pWpk;
    cudaGetSymbolAddress((void**)&pXT,   g_xT);
    cudaGetSymbolAddress((void**)&pD,    g_D);
    cudaGetSymbolAddress((void**)&pAnch, g_anchor);
    cudaGetSymbolAddress((void**)&pT,    g_T);
    cudaGetSymbolAddress((void**)&pU,    g_U);
    cudaGetSymbolAddress((void**)&pV,    g_V);
    cudaGetSymbolAddress((void**)&pZ,    g_Z);
    cudaGetSymbolAddress((void**)&pZ1,   g_Z1);
    cudaGetSymbolAddress((void**)&pZ2,   g_Z2);
    cudaGetSymbolAddress((void**)&pC1,   g_const1);
    cudaGetSymbolAddress((void**)&pSsum, g_ssum);
    cudaGetSymbolAddress((void**)&pSsq,  g_ssq);
    cudaGetSymbolAddress((void**)&pCoef, g_coef);
    cudaGetSymbolAddress((void**)&pInv,  g_invstd);
    cudaGetSymbolAddress((void**)&pDummy,g_dummy);
    cudaGetSymbolAddress((void**)&pWpk,  g_Wpk);

    const int WSLOT = 2*128*128;                       // bf16 elements per weight slot
    const int smem64  = (2*64*36 + 2*128*36) * 4;      // 55296
    const int smem128 = (2*64*68 + 2*128*68) * 4;      // 104448
    cudaFuncSetAttribute(knn_kernel, cudaFuncAttributeMaxDynamicSharedMemorySize, 65536);
    cudaFuncSetAttribute(mma_gemm<64,  false, 0, false>, cudaFuncAttributeMaxDynamicSharedMemorySize, smem64);
    cudaFuncSetAttribute(mma_gemm<64,  false, 2, true >, cudaFuncAttributeMaxDynamicSharedMemorySize, smem64);
    cudaFuncSetAttribute(mma_gemm<128, true,  1, true >, cudaFuncAttributeMaxDynamicSharedMemorySize, smem128);
    cudaFuncSetAttribute(mma_gemm<128, false, 1, true >, cudaFuncAttributeMaxDynamicSharedMemorySize, smem128);

    const float invM  = 1.f / (float)M_TOT;
    const float invBN = 1.f / (float)BN_TOT;

    // launches 1-3 (ncu captures the 4th launch = shadow GEMM)
    zero_stats_kernel<<<1, 1024>>>();
    prep_w_kernel<<<64, 256>>>(w01, nullptr, 0, 128, 128, pWpk + 2*WSLOT);
    prep_w_kernel<<<32, 256>>>(wt,  alpha,   0, 128,  64, pWpk + 0*WSLOT);

    // launch 4: SHADOW U-GEMM (profiling target; stale deterministic inputs,
    // writes g_U which the real U-GEMM later fully overwrites, stats -> dummy)
    mma_gemm<128, true, 1, true><<<3072, 256, smem128>>>(
        pT, pWpk + 2*WSLOT, pU, pCoef + 0, pCoef + 128, b01,
        nullptr, nullptr, nullptr, pDummy, pDummy + 128);

    prep_w_kernel<<<32, 256>>>(wt,  nullptr, 64, 128, 64, pWpk + 1*WSLOT);
    prep_w_kernel<<<64, 256>>>(w02, nullptr, 0, 128, 128, pWpk + 3*WSLOT);
    prep_w_kernel<<<64, 256>>>(w11, nullptr, 0, 128, 128, pWpk + 4*WSLOT);
    prep_w_kernel<<<64, 256>>>(w12, nullptr, 0, 128, 128, pWpk + 5*WSLOT);
    transpose_x_kernel<<<dim3(N_/32, CIN_/32, B_), dim3(32, 8)>>>(x);
    knn_kernel<<<dim3(N_/128, B_), 128, 65536>>>(xyz);
    const1_kernel<<<1, 128>>>(wt, beta, bt);

    gather_diff_kernel<<<M_TOT/8, 256>>>();
    std_fin_kernel<<<1, 32>>>();

    // anchor = pts @ Wp^T
    mma_gemm<64, false, 0, false><<<BN_TOT/64, 256, smem64>>>(
        pXT, pWpk + 1*WSLOT, pAnch, nullptr, nullptr, nullptr,
        nullptr, nullptr, nullptr, nullptr, nullptr);

    // T = invstd_b * (D @ Wa^T) + anchor + const1   (stats 0 fused)
    mma_gemm<64, false, 2, true><<<M_TOT/64, 256, smem64>>>(
        pD, pWpk + 0*WSLOT, pT, nullptr, nullptr, nullptr,
        pInv, pAnch, pC1, pSsum + 0, pSsq + 0);
    bn_fin_kernel<<<1, 128>>>(0, invM, gt, btt);

    // U = relu(bn0(T)) @ w01^T + b01   (stats 1 fused)
    mma_gemm<128, true, 1, true><<<M_TOT/64, 256, smem128>>>(
        pT, pWpk + 2*WSLOT, pU, pCoef + 0, pCoef + 128, b01,
        nullptr, nullptr, nullptr, pSsum + 128, pSsq + 128);
    bn_fin_kernel<<<1, 128>>>(1, invM, g01, bb01);

    // V = relu(bn1(U)) @ w02^T + b02   (stats 2 fused)
    mma_gemm<128, true, 1, true><<<M_TOT/64, 256, smem128>>>(
        pU, pWpk + 3*WSLOT, pV, pCoef + 256, pCoef + 384, b02,
        nullptr, nullptr, nullptr, pSsum + 256, pSsq + 256);
    bn_fin_kernel<<<1, 128>>>(2, invM, g02, bb02);

    pool_kernel<<<BN_TOT, 128>>>();

    // Z1 = Z @ w11^T + b11   (stats 3 fused)
    mma_gemm<128, false, 1, true><<<BN_TOT/64, 256, smem128>>>(
        pZ, pWpk + 4*WSLOT, pZ1, nullptr, nullptr, b11,
        nullptr, nullptr, nullptr, pSsum + 384, pSsq + 384);
    bn_fin_kernel<<<1, 128>>>(3, invBN, g11, bb11);

    // Z2 = relu(bn3(Z1)) @ w12^T + b12   (stats 4 fused)
    mma_gemm<128, true, 1, true><<<BN_TOT/64, 256, smem128>>>(
        pZ1, pWpk + 5*WSLOT, pZ2, pCoef + 3*256, pCoef + 3*256 + 128, b12,
        nullptr, nullptr, nullptr, pSsum + 512, pSsq + 512);
    bn_fin_kernel<<<1, 128>>>(4, invBN, g12, bb12);

    out_kernel<<<dim3(N_/32, COUT_/32, B_), dim3(32, 8)>>>(out);
}

// round 12
// speedup vs baseline: 1.6948x; 1.2143x over previous
#include <cuda_runtime.h>
#include <cuda_bf16.h>
#include <stdint.h>
#include <math.h>

#define B_    4
#define N_    4096
#define K_    24
#define CIN_  64
#define COUT_ 128
#define BN_TOT (B_*N_)            // 16384
#define M_TOT  (BN_TOT*K_)        // 393216
#define EPS_  1e-5f
#define GRID_P 296                // persistent grid: 2 CTAs/SM x 148

// ======================= scratch =======================
__device__ float g_xT[BN_TOT*CIN_];
__device__ int   g_idx[M_TOT];
__device__ float g_D[(size_t)M_TOT*CIN_];
__device__ float g_anchor[BN_TOT*COUT_];
__device__ float g_T[(size_t)M_TOT*COUT_];
__device__ float g_U[(size_t)M_TOT*COUT_];
__device__ float g_V[(size_t)M_TOT*COUT_];
__device__ float g_Z [BN_TOT*COUT_];
__device__ float g_Z1[BN_TOT*COUT_];
__device__ float g_Z2[BN_TOT*COUT_];
__device__ float g_const1[COUT_];
__device__ float g_ssum[5*128];
__device__ float g_ssq [5*128];
__device__ float g_coef[5*256];
__device__ float g_bsum[B_];
__device__ float g_bsq [B_];
__device__ float g_invstd[B_];
__device__ __nv_bfloat16 g_Wpk[6*2*128*128];   // 6 weights x (hi | lo), packed [o][k]

// ======================= asm helpers =======================
__device__ __forceinline__ uint32_t smem_u32(const void* p) {
    uint32_t a;
    asm("{ .reg .u64 t; cvta.to.shared.u64 t, %1; cvt.u32.u64 %0, t; }" : "=r"(a) : "l"(p));
    return a;
}
__device__ __forceinline__ void mma16816(float* c, const uint32_t* a, uint32_t b0, uint32_t b1) {
    asm volatile(
        "mma.sync.aligned.m16n8k16.row.col.f32.bf16.bf16.f32 "
        "{%0,%1,%2,%3}, {%4,%5,%6,%7}, {%8,%9}, {%0,%1,%2,%3};"
        : "+f"(c[0]), "+f"(c[1]), "+f"(c[2]), "+f"(c[3])
        : "r"(a[0]), "r"(a[1]), "r"(a[2]), "r"(a[3]), "r"(b0), "r"(b1));
}
__device__ __forceinline__ void ldsm4(uint32_t& r0, uint32_t& r1, uint32_t& r2, uint32_t& r3,
                                      uint32_t addr) {
    asm volatile("ldmatrix.sync.aligned.m8n8.x4.shared.b16 {%0,%1,%2,%3}, [%4];"
                 : "=r"(r0), "=r"(r1), "=r"(r2), "=r"(r3) : "r"(addr));
}

// ======================= utility kernels =======================
__global__ void zero_stats_kernel() {
    int i = threadIdx.x;              // 1024 threads
    if (i < 640) { g_ssum[i] = 0.f; g_ssq[i] = 0.f; }
    if (i < B_) { g_bsum[i] = 0.f; g_bsq[i] = 0.f; }
}

__global__ void transpose_x_kernel(const float* __restrict__ x) {
    __shared__ float tile[32][33];
    int b = blockIdx.z;
    int n0 = blockIdx.x * 32, c0 = blockIdx.y * 32;
    int tx = threadIdx.x, ty = threadIdx.y;
    #pragma unroll
    for (int rr = 0; rr < 4; ++rr) {
        int c = c0 + ty + rr*8;
        tile[ty + rr*8][tx] = x[((size_t)b*CIN_ + c)*N_ + n0 + tx];
    }
    __syncthreads();
    #pragma unroll
    for (int rr = 0; rr < 4; ++rr) {
        int n = n0 + ty + rr*8;
        g_xT[((size_t)b*N_ + n)*CIN_ + c0 + tx] = tile[tx][ty + rr*8];
    }
}

// split weight into bf16 hi/lo, packed [o][k]; hi tile then lo tile
__global__ void prep_w_kernel(const float* __restrict__ src,
                              const float* __restrict__ alpha,
                              int colOff, int srcStride, int KD,
                              __nv_bfloat16* __restrict__ dst) {
    int tot = 128 * KD;
    for (int i = blockIdx.x*blockDim.x + threadIdx.x; i < tot; i += gridDim.x*blockDim.x) {
        int o = i / KD, k = i - o*KD;
        float v = src[o*srcStride + colOff + k];
        if (alpha != nullptr) v *= alpha[k];
        __nv_bfloat16 hi = __float2bfloat16_rn(v);
        __nv_bfloat16 lo = __float2bfloat16_rn(v - __bfloat162float(hi));
        dst[i] = hi;
        dst[tot + i] = lo;
    }
}

__global__ void const1_kernel(const float* __restrict__ wt,
                              const float* __restrict__ beta,
                              const float* __restrict__ bt) {
    int o = threadIdx.x;
    float s = bt[o];
    #pragma unroll 8
    for (int c = 0; c < CIN_; ++c) s += wt[o*128 + c] * beta[c];
    g_const1[o] = s;
}

// ======================= kNN =======================
__global__ void knn_kernel(const float* __restrict__ xyz) {
    extern __shared__ float s[];
    float* sx = s;
    float* sy = s + N_;
    float* sz = s + 2*N_;
    float* sq = s + 3*N_;
    int b = blockIdx.y;
    const float* xb = xyz + (size_t)b*3*N_;
    for (int i = threadIdx.x; i < N_; i += blockDim.x) {
        float X = xb[i], Y = xb[N_ + i], Z = xb[2*N_ + i];
        sx[i] = X; sy[i] = Y; sz[i] = Z;
        sq[i] = X*X + Y*Y + Z*Z;
    }
    __syncthreads();
    int q = blockIdx.x * blockDim.x + threadIdx.x;
    float qx = sx[q], qy = sy[q], qz = sz[q], qs = sq[q];
    float kd[K_]; int ki[K_];
    #pragma unroll
    for (int t = 0; t < K_; ++t) { kd[t] = 3.4e38f; ki[t] = 0; }
    float worst = 3.4e38f;
    for (int j = 0; j < N_; ++j) {
        float d = qs + sq[j] - 2.f*(qx*sx[j] + qy*sy[j] + qz*sz[j]);
        if (d < worst) {
            int p = K_ - 1;
            while (p > 0 && kd[p-1] > d) { kd[p] = kd[p-1]; ki[p] = ki[p-1]; --p; }
            kd[p] = d; ki[p] = j;
            worst = kd[K_-1];
        }
    }
    int* o = g_idx + ((size_t)b*N_ + q)*K_;
    #pragma unroll
    for (int t = 0; t < K_; ++t) o[t] = ki[t];
}

// ======================= gather + diff + batch std =======================
__global__ void gather_diff_kernel() {
    __shared__ float bs[8], bs2[8];
    int wid = threadIdx.x >> 5, lane = threadIdx.x & 31;
    int m = blockIdx.x * 8 + wid;
    int b = m / (N_*K_);
    int nk = m - b*(N_*K_);
    int n = nk / K_;
    int j = g_idx[m];
    const float2* src = reinterpret_cast<const float2*>(g_xT + ((size_t)b*N_ + j)*CIN_);
    const float2* anc = reinterpret_cast<const float2*>(g_xT + ((size_t)b*N_ + n)*CIN_);
    float2 gv = src[lane];
    float2 pv = anc[lane];
    float2 dv = make_float2(gv.x - pv.x, gv.y - pv.y);
    reinterpret_cast<float2*>(g_D + (size_t)m*CIN_)[lane] = dv;
    float s  = dv.x + dv.y;
    float s2 = dv.x*dv.x + dv.y*dv.y;
    #pragma unroll
    for (int off = 16; off; off >>= 1) {
        s  += __shfl_xor_sync(0xffffffffu, s,  off);
        s2 += __shfl_xor_sync(0xffffffffu, s2, off);
    }
    if (lane == 0) { bs[wid] = s; bs2[wid] = s2; }
    __syncthreads();
    if (threadIdx.x == 0) {
        float S = 0.f, S2 = 0.f;
        #pragma unroll
        for (int i = 0; i < 8; ++i) { S += bs[i]; S2 += bs2[i]; }
        atomicAdd(&g_bsum[b], S);
        atomicAdd(&g_bsq[b],  S2);
    }
}

__global__ void std_fin_kernel() {
    int b = threadIdx.x;
    if (b < B_) {
        const float cnt = (float)(N_*K_*CIN_);
        float mean = g_bsum[b] / cnt;
        float var  = (g_bsq[b] - cnt*mean*mean) / (cnt - 1.f);
        var = fmaxf(var, 0.f);
        g_invstd[b] = 1.f / (sqrtf(var) + EPS_);
    }
}

// ======================= persistent mma.sync GEMM ==========================
// C[m, o] = pre(A[m, :]) @ W[o, :]^T  + epilogue.   CTA tile: 64 x 128.
// Persistent: each CTA stages B (hi/lo) ONCE, then loops over M-tiles.
// Warp tile: 32 x 32.  EPI: 0 none, 1 +bias, 2 acc*invstd+anchor+const1.
// ST: per-channel sum/sumsq accumulated in regs across tiles, flushed once.
template<int KDIM, bool PRE, int EPI, bool ST>
__global__ __launch_bounds__(256, 2)
void mma_gemm(int ntiles,
              const float* __restrict__ A,
              const __nv_bfloat16* __restrict__ Wpk,
              float* __restrict__ C,
              const float* __restrict__ preA, const float* __restrict__ preC,
              const float* __restrict__ bias,
              const float* __restrict__ invstd,
              const float* __restrict__ anchor,
              const float* __restrict__ cnst,
              float* __restrict__ stat_sum,
              float* __restrict__ stat_sq) {
    constexpr int W = KDIM/2 + 4;          // b32 words per row
    constexpr int TILEA = 64 * W;          // words per A component tile
    constexpr int TILEB = 128 * W;         // words per B component tile
    extern __shared__ uint32_t sm32[];
    __shared__ float s_stat[256];
    uint32_t* Ahi = sm32;
    uint32_t* Alo = sm32 + TILEA;
    uint32_t* Bhi = sm32 + 2*TILEA;
    uint32_t* Blo = Bhi + TILEB;
    const int tid = threadIdx.x;
    const int lane = tid & 31, wid = tid >> 5;
    const int wy = wid & 1, wx = wid >> 1;     // warp tile: rows wy*32, cols wx*32

    if (ST && tid < 256) s_stat[tid] = 0.f;

    // ---- stage B once (packed hi|lo -> padded) ----
    {
        constexpr int NB = 128 * KDIM / 8;     // uint4 per component tile
        const uint4* src = reinterpret_cast<const uint4*>(Wpk);
        #pragma unroll 2
        for (int i = tid; i < NB; i += 256) {
            int r = i / (KDIM/8), cb = i - r*(KDIM/8);
            *reinterpret_cast<uint4*>(Bhi + r*W + cb*4) = src[i];
            *reinterpret_cast<uint4*>(Blo + r*W + cb*4) = src[NB + i];
        }
    }

    // ---- fragment smem addresses (ldmatrix.x4 lane mapping) ----
    const uint32_t sbase = smem_u32(sm32);
    const uint32_t aBase = sbase + (uint32_t)(((wy*32 + (lane & 15))*W + (lane >> 4)*4) * 4);
    const uint32_t bBase = sbase + (uint32_t)((2*TILEA +
                           (wx*32 + ((lane>>4)&1)*8 + (lane&7))*W + ((lane>>3)&1)*4) * 4);

    const int r = lane >> 2, q = lane & 3;
    float cs[8], cq[8];
    if (ST) {
        #pragma unroll
        for (int j = 0; j < 8; ++j) { cs[j] = 0.f; cq[j] = 0.f; }
    }

    for (int t = blockIdx.x; t < ntiles; t += gridDim.x) {
        const int m0 = t * 64;
        __syncthreads();   // prev mainloop done (and B staged, first iter)

        // ---- stage A tile: fp32 load, optional affine+relu, hi/lo split ----
        {
            constexpr int NCH = KDIM / 8;
            #pragma unroll
            for (int id = tid; id < 64*NCH; id += 256) {
                int rr = id / NCH, cb = (id - rr*NCH) * 8;
                const float4* ap = reinterpret_cast<const float4*>(A + (size_t)(m0 + rr)*KDIM + cb);
                float4 v0 = ap[0], v1 = ap[1];
                float va[8] = {v0.x, v0.y, v0.z, v0.w, v1.x, v1.y, v1.z, v1.w};
                if (PRE) {
                    const float4* pa = reinterpret_cast<const float4*>(preA + cb);
                    const float4* pc = reinterpret_cast<const float4*>(preC + cb);
                    float4 a0 = pa[0], a1 = pa[1], c0v = pc[0], c1v = pc[1];
                    float aa[8] = {a0.x,a0.y,a0.z,a0.w,a1.x,a1.y,a1.z,a1.w};
                    float cc[8] = {c0v.x,c0v.y,c0v.z,c0v.w,c1v.x,c1v.y,c1v.z,c1v.w};
                    #pragma unroll
                    for (int j = 0; j < 8; ++j) va[j] = fmaxf(fmaf(aa[j], va[j], cc[j]), 0.f);
                }
                uint32_t h[4], l[4];
                #pragma unroll
                for (int j = 0; j < 4; ++j) {
                    float a = va[2*j], b = va[2*j+1];
                    __nv_bfloat16 ha = __float2bfloat16_rn(a);
                    __nv_bfloat16 hb = __float2bfloat16_rn(b);
                    __nv_bfloat16 la = __float2bfloat16_rn(a - __bfloat162float(ha));
                    __nv_bfloat16 lb = __float2bfloat16_rn(b - __bfloat162float(hb));
                    h[j] = (uint32_t)__bfloat16_as_ushort(ha) | ((uint32_t)__bfloat16_as_ushort(hb) << 16);
                    l[j] = (uint32_t)__bfloat16_as_ushort(la) | ((uint32_t)__bfloat16_as_ushort(lb) << 16);
                }
                *reinterpret_cast<uint4*>(Ahi + rr*W + (cb >> 1)) = make_uint4(h[0], h[1], h[2], h[3]);
                *reinterpret_cast<uint4*>(Alo + rr*W + (cb >> 1)) = make_uint4(l[0], l[1], l[2], l[3]);
            }
        }
        __syncthreads();

        // ---- mainloop ----
        float acc[2][4][4];
        #pragma unroll
        for (int mi = 0; mi < 2; ++mi)
            #pragma unroll
            for (int ni = 0; ni < 4; ++ni)
                #pragma unroll
                for (int j = 0; j < 4; ++j) acc[mi][ni][j] = 0.f;

        #pragma unroll
        for (int ks = 0; ks < KDIM/16; ++ks) {
            const uint32_t koff = (uint32_t)(ks * 32);       // 8 words = 32B per kstep
            uint32_t afh[2][4], afl[2][4];
            ldsm4(afh[0][0], afh[0][1], afh[0][2], afh[0][3], aBase + koff);
            ldsm4(afh[1][0], afh[1][1], afh[1][2], afh[1][3], aBase + (uint32_t)(16*W*4) + koff);
            ldsm4(afl[0][0], afl[0][1], afl[0][2], afl[0][3], aBase + (uint32_t)(TILEA*4) + koff);
            ldsm4(afl[1][0], afl[1][1], afl[1][2], afl[1][3], aBase + (uint32_t)((TILEA + 16*W)*4) + koff);
            #pragma unroll
            for (int nb = 0; nb < 2; ++nb) {
                const uint32_t noff = (uint32_t)(nb*16*W*4) + koff;
                uint32_t h0, h1, h2, h3, l0, l1, l2, l3;
                ldsm4(h0, h1, h2, h3, bBase + noff);
                ldsm4(l0, l1, l2, l3, bBase + (uint32_t)(TILEB*4) + noff);
                #pragma unroll
                for (int mi = 0; mi < 2; ++mi) {
                    mma16816(acc[mi][2*nb],   afh[mi], h0, h1);
                    mma16816(acc[mi][2*nb+1], afh[mi], h2, h3);
                    mma16816(acc[mi][2*nb],   afh[mi], l0, l1);
                    mma16816(acc[mi][2*nb+1], afh[mi], l2, l3);
                    mma16816(acc[mi][2*nb],   afl[mi], h0, h1);
                    mma16816(acc[mi][2*nb+1], afl[mi], h2, h3);
                }
            }
        }

        // ---- epilogue (stats accumulate in regs) ----
        float inv = 0.f;
        if (EPI == 2) inv = invstd[m0 / (N_*K_)];
        #pragma unroll
        for (int mi = 0; mi < 2; ++mi) {
            #pragma unroll
            for (int half = 0; half < 2; ++half) {
                const int row = m0 + wy*32 + mi*16 + r + half*8;
                float* crow = C + (size_t)row * COUT_;
                const float* arow = (EPI == 2) ? anchor + (size_t)(row / K_) * COUT_ : nullptr;
                #pragma unroll
                for (int ni = 0; ni < 4; ++ni) {
                    const int col = wx*32 + ni*8 + q*2;
                    float v0 = acc[mi][ni][half*2 + 0];
                    float v1 = acc[mi][ni][half*2 + 1];
                    if (EPI == 2) {
                        v0 = fmaf(v0, inv, arow[col]     + cnst[col]);
                        v1 = fmaf(v1, inv, arow[col + 1] + cnst[col + 1]);
                    } else if (EPI == 1) {
                        v0 += bias[col];
                        v1 += bias[col + 1];
                    }
                    if (ST) {
                        cs[ni*2]     += v0;  cq[ni*2]     = fmaf(v0, v0, cq[ni*2]);
                        cs[ni*2 + 1] += v1;  cq[ni*2 + 1] = fmaf(v1, v1, cq[ni*2 + 1]);
                    }
                    *reinterpret_cast<float2*>(crow + col) = make_float2(v0, v1);
                }
            }
        }
    }

    // ---- stats flush (once per CTA) ----
    if (ST) {
        #pragma unroll
        for (int j = 0; j < 8; ++j) {
            #pragma unroll
            for (int off = 4; off < 32; off <<= 1) {
                cs[j] += __shfl_xor_sync(0xffffffffu, cs[j], off);
                cq[j] += __shfl_xor_sync(0xffffffffu, cq[j], off);
            }
        }
        __syncthreads();
        if (r == 0) {
            #pragma unroll
            for (int j = 0; j < 8; ++j) {
                int col = wx*32 + (j >> 1)*8 + q*2 + (j & 1);
                atomicAdd(&s_stat[col], cs[j]);
                atomicAdd(&s_stat[128 + col], cq[j]);
            }
        }
        __syncthreads();
        if (tid < 128) {
            atomicAdd(&stat_sum[tid], s_stat[tid]);
            atomicAdd(&stat_sq[tid],  s_stat[128 + tid]);
        }
    }
}

// ======================= BN finalize =======================
__global__ void bn_fin_kernel(int stage, float inv_cnt,
                              const float* __restrict__ gamma,
                              const float* __restrict__ betab) {
    int o = threadIdx.x;
    float mean = g_ssum[stage*128 + o] * inv_cnt;
    float var  = g_ssq [stage*128 + o] * inv_cnt - mean*mean;
    var = fmaxf(var, 0.f);
    float a = gamma[o] / sqrtf(var + EPS_);
    g_coef[stage*256 + o]       = a;
    g_coef[stage*256 + 128 + o] = betab[o] - mean*a;
}

// ======================= residual + relu + maxpool over K =======================
__global__ void pool_kernel() {
    int bn = blockIdx.x;
    int o  = threadIdx.x;
    float A2 = g_coef[2*256 + o],       C2 = g_coef[2*256 + 128 + o];
    float A0 = g_coef[o],               C0 = g_coef[128 + o];
    const float* vp = g_V + (size_t)bn*K_*COUT_ + o;
    const float* tp = g_T + (size_t)bn*K_*COUT_ + o;
    float mx = -3.4e38f;
    #pragma unroll 8
    for (int k = 0; k < K_; ++k) {
        float v = fmaf(A2, vp[k*COUT_], C2) + fmaxf(fmaf(A0, tp[k*COUT_], C0), 0.f);
        mx = fmaxf(mx, fmaxf(v, 0.f));
    }
    g_Z[(size_t)bn*COUT_ + o] = mx;
}

// ======================= final BN + residual + relu + transpose =======================
__global__ void out_kernel(float* __restrict__ out) {
    __shared__ float tile[32][33];
    int b = blockIdx.z;
    int n0 = blockIdx.x * 32, o0 = blockIdx.y * 32;
    int tx = threadIdx.x, ty = threadIdx.y;
    float a5 = g_coef[4*256 + o0 + tx];
    float c5 = g_coef[4*256 + 128 + o0 + tx];
    #pragma unroll
    for (int rr = 0; rr < 4; ++rr) {
        int n  = n0 + ty + rr*8;
        size_t bn = (size_t)b*N_ + n;
        float v = fmaf(a5, g_Z2[bn*COUT_ + o0 + tx], c5) + g_Z[bn*COUT_ + o0 + tx];
        tile[ty + rr*8][tx] = fmaxf(v, 0.f);
    }
    __syncthreads();
    #pragma unroll
    for (int rr = 0; rr < 4; ++rr) {
        int o = o0 + ty + rr*8;
        out[((size_t)b*COUT_ + o)*N_ + n0 + tx] = tile[tx][ty + rr*8];
    }
}

// ======================= host =======================
extern "C" void kernel_launch(void* const* d_in, const int* in_sizes, int n_in,
                              void* d_out, int out_size) {
    const float* x    = (const float*)d_in[0];
    const float* xyz  = (const float*)d_in[1];
    const float* alpha= (const float*)d_in[2];
    const float* beta = (const float*)d_in[3];
    const float* wt   = (const float*)d_in[4];
    const float* bt   = (const float*)d_in[5];
    const float* gt   = (const float*)d_in[6];
    const float* btt  = (const float*)d_in[7];
    const float* w01  = (const float*)d_in[8];
    const float* b01  = (const float*)d_in[9];
    const float* g01  = (const float*)d_in[10];
    const float* bb01 = (const float*)d_in[11];
    const float* w02  = (const float*)d_in[12];
    const float* b02  = (const float*)d_in[13];
    const float* g02  = (const float*)d_in[14];
    const float* bb02 = (const float*)d_in[15];
    const float* w11  = (const float*)d_in[16];
    const float* b11  = (const float*)d_in[17];
    const float* g11  = (const float*)d_in[18];
    const float* bb11 = (const float*)d_in[19];
    const float* w12  = (const float*)d_in[20];
    const float* b12  = (const float*)d_in[21];
    const float* g12  = (const float*)d_in[22];
    const float* bb12 = (const float*)d_in[23];
    float* out = (float*)d_out;

    float *pXT, *pD, *pAnch, *pT, *pU, *pV, *pZ, *pZ1, *pZ2;
    float *pC1, *pSsum, *pSsq, *pCoef, *pInv;
    __nv_bfloat16* pWpk;
    cudaGetSymbolAddress((void**)&pXT,   g_xT);
    cudaGetSymbolAddress((void**)&pD,    g_D);
    cudaGetSymbolAddress((void**)&pAnch, g_anchor);
    cudaGetSymbolAddress((void**)&pT,    g_T);
    cudaGetSymbolAddress((void**)&pU,    g_U);
    cudaGetSymbolAddress((void**)&pV,    g_V);
    cudaGetSymbolAddress((void**)&pZ,    g_Z);
    cudaGetSymbolAddress((void**)&pZ1,   g_Z1);
    cudaGetSymbolAddress((void**)&pZ2,   g_Z2);
    cudaGetSymbolAddress((void**)&pC1,   g_const1);
    cudaGetSymbolAddress((void**)&pSsum, g_ssum);
    cudaGetSymbolAddress((void**)&pSsq,  g_ssq);
    cudaGetSymbolAddress((void**)&pCoef, g_coef);
    cudaGetSymbolAddress((void**)&pInv,  g_invstd);
    cudaGetSymbolAddress((void**)&pWpk,  g_Wpk);

    const int WSLOT = 2*128*128;                       // bf16 elements per weight slot
    const int smem64  = (2*64*36 + 2*128*36) * 4;      // 55296
    const int smem128 = (2*64*68 + 2*128*68) * 4;      // 104448
    cudaFuncSetAttribute(knn_kernel, cudaFuncAttributeMaxDynamicSharedMemorySize, 65536);
    cudaFuncSetAttribute(mma_gemm<64,  false, 0, false>, cudaFuncAttributeMaxDynamicSharedMemorySize, smem64);
    cudaFuncSetAttribute(mma_gemm<64,  false, 2, true >, cudaFuncAttributeMaxDynamicSharedMemorySize, smem64);
    cudaFuncSetAttribute(mma_gemm<128, true,  1, true >, cudaFuncAttributeMaxDynamicSharedMemorySize, smem128);
    cudaFuncSetAttribute(mma_gemm<128, false, 1, true >, cudaFuncAttributeMaxDynamicSharedMemorySize, smem128);

    const float invM  = 1.f / (float)M_TOT;
    const float invBN = 1.f / (float)BN_TOT;
    const int TILES_BIG = M_TOT / 64;     // 6144
    const int TILES_SM  = BN_TOT / 64;    // 256

    // launches 1-3 (ncu -s 5 -c 1 captures launch 4 = knn_kernel)
    zero_stats_kernel<<<1, 1024>>>();
    prep_w_kernel<<<64, 256>>>(w01, nullptr, 0, 128, 128, pWpk + 2*WSLOT);
    prep_w_kernel<<<32, 256>>>(wt,  alpha,   0, 128,  64, pWpk + 0*WSLOT);
    // launch 4: kNN (profiled this round)
    knn_kernel<<<dim3(N_/128, B_), 128, 65536>>>(xyz);

    prep_w_kernel<<<32, 256>>>(wt,  nullptr, 64, 128, 64, pWpk + 1*WSLOT);
    prep_w_kernel<<<64, 256>>>(w02, nullptr, 0, 128, 128, pWpk + 3*WSLOT);
    prep_w_kernel<<<64, 256>>>(w11, nullptr, 0, 128, 128, pWpk + 4*WSLOT);
    prep_w_kernel<<<64, 256>>>(w12, nullptr, 0, 128, 128, pWpk + 5*WSLOT);
    transpose_x_kernel<<<dim3(N_/32, CIN_/32, B_), dim3(32, 8)>>>(x);
    const1_kernel<<<1, 128>>>(wt, beta, bt);

    gather_diff_kernel<<<M_TOT/8, 256>>>();
    std_fin_kernel<<<1, 32>>>();

    // anchor = pts @ Wp^T
    mma_gemm<64, false, 0, false><<<TILES_SM, 256, smem64>>>(
        TILES_SM, pXT, pWpk + 1*WSLOT, pAnch, nullptr, nullptr, nullptr,
        nullptr, nullptr, nullptr, nullptr, nullptr);

    // T = invstd_b * (D @ Wa^T) + anchor + const1   (stats 0 fused)
    mma_gemm<64, false, 2, true><<<GRID_P, 256, smem64>>>(
        TILES_BIG, pD, pWpk + 0*WSLOT, pT, nullptr, nullptr, nullptr,
        pInv, pAnch, pC1, pSsum + 0, pSsq + 0);
    bn_fin_kernel<<<1, 128>>>(0, invM, gt, btt);

    // U = relu(bn0(T)) @ w01^T + b01   (stats 1 fused)
    mma_gemm<128, true, 1, true><<<GRID_P, 256, smem128>>>(
        TILES_BIG, pT, pWpk + 2*WSLOT, pU, pCoef + 0, pCoef + 128, b01,
        nullptr, nullptr, nullptr, pSsum + 128, pSsq + 128);
    bn_fin_kernel<<<1, 128>>>(1, invM, g01, bb01);

    // V = relu(bn1(U)) @ w02^T + b02   (stats 2 fused)
    mma_gemm<128, true, 1, true><<<GRID_P, 256, smem128>>>(
        TILES_BIG, pU, pWpk + 3*WSLOT, pV, pCoef + 256, pCoef + 384, b02,
        nullptr, nullptr, nullptr, pSsum + 256, pSsq + 256);
    bn_fin_kernel<<<1, 128>>>(2, invM, g02, bb02);

    pool_kernel<<<BN_TOT, 128>>>();

    // Z1 = Z @ w11^T + b11   (stats 3 fused)
    mma_gemm<128, false, 1, true><<<TILES_SM, 256, smem128>>>(
        TILES_SM, pZ, pWpk + 4*WSLOT, pZ1, nullptr, nullptr, b11,
        nullptr, nullptr, nullptr, pSsum + 384, pSsq + 384);
    bn_fin_kernel<<<1, 128>>>(3, invBN, g11, bb11);

    // Z2 = relu(bn3(Z1)) @ w12^T + b12   (stats 4 fused)
    mma_gemm<128, true, 1, true><<<TILES_SM, 256, smem128>>>(
        TILES_SM, pZ1, pWpk + 5*WSLOT, pZ2, pCoef + 3*256, pCoef + 3*256 + 128, b12,
        nullptr, nullptr, nullptr, pSsum + 512, pSsq + 512);
    bn_fin_kernel<<<1, 128>>>(4, invBN, g12, bb12);

    out_kernel<<<dim3(N_/32, COUT_/32, B_), dim3(32, 8)>>>(out);
}